// round 9
// baseline (speedup 1.0000x reference)
#include <cuda_runtime.h>
#include <cuda_bf16.h>
#include <cstdint>

// ---------------------------------------------------------------------------
// tf32 helpers
// ---------------------------------------------------------------------------
__device__ __forceinline__ float tf32r(float f) {
    uint32_t o; asm("cvt.rna.tf32.f32 %0,%1;" : "=r"(o) : "f"(f));
    return __uint_as_float(o);
}
__device__ __forceinline__ void mma4(float* c, uint32_t a0, uint32_t a1, uint32_t b0) {
    asm("mma.sync.aligned.m16n8k4.row.col.f32.tf32.tf32.f32 "
        "{%0,%1,%2,%3},{%4,%5},{%6},{%0,%1,%2,%3};"
        : "+f"(c[0]), "+f"(c[1]), "+f"(c[2]), "+f"(c[3])
        : "r"(a0), "r"(a1), "r"(b0));
}
__device__ __forceinline__ uint32_t fbits(float f) { return __float_as_uint(f); }

// ---------------------------------------------------------------------------
// Scratch
// ---------------------------------------------------------------------------
__device__ float g_s1[1024 * 32 * 32 * 36];   // conv1 out, NHWC
__device__ float g_s2[1024 * 16 * 16 * 36];   // conv2 out, NHWC
__device__ float g_s3[1024 * 36 * 8 * 8];     // conv3 out, NCHW (flatten 2304)
__device__ float g_h [1024 * 12];
__device__ float g_p1[1024 * 12 * 32 * 32];   // private conv out, NCHW (12288)
__device__ float g_pf[1024 * 12];

// ---------------------------------------------------------------------------
// Epilogue: fragment-level 2x2 maxpool via shfl, bias+act, store.
// acc rows map: c0/c1 -> (dy=g>>2, dx=g&3, oc=2t / 2t+1), c2/c3 -> dy+2.
// ---------------------------------------------------------------------------
template <int OCR, int PO, bool LEAKY, bool NCHW_OUT>
__device__ __forceinline__ void epilogue_tile(const float acc[][4], int NF,
                                              int ty, int tx, int g, int t,
                                              const float* b_s, float* out) {
    for (int nf = 0; nf < NF; nf++) {
        float v0 = acc[nf][0], v1 = acc[nf][1], v2 = acc[nf][2], v3 = acc[nf][3];
        v0 = fmaxf(v0, __shfl_xor_sync(0xffffffffu, v0, 4));
        v1 = fmaxf(v1, __shfl_xor_sync(0xffffffffu, v1, 4));
        v2 = fmaxf(v2, __shfl_xor_sync(0xffffffffu, v2, 4));
        v3 = fmaxf(v3, __shfl_xor_sync(0xffffffffu, v3, 4));
        v0 = fmaxf(v0, __shfl_xor_sync(0xffffffffu, v0, 16));
        v1 = fmaxf(v1, __shfl_xor_sync(0xffffffffu, v1, 16));
        v2 = fmaxf(v2, __shfl_xor_sync(0xffffffffu, v2, 16));
        v3 = fmaxf(v3, __shfl_xor_sync(0xffffffffu, v3, 16));
        int oc = nf * 8 + 2 * t;
        if (((g & 1) == 0) && (g < 4) && oc < OCR) {
            int px  = tx * 2 + (g >> 1);
            int py0 = ty * 2;
            float b0 = b_s[oc], b1 = b_s[oc + 1];
            float o00 = v0 + b0, o01 = v1 + b1, o10 = v2 + b0, o11 = v3 + b1;
            if (LEAKY) {
                o00 = o00 > 0.f ? o00 : 0.001f * o00;
                o01 = o01 > 0.f ? o01 : 0.001f * o01;
                o10 = o10 > 0.f ? o10 : 0.001f * o10;
                o11 = o11 > 0.f ? o11 : 0.001f * o11;
            } else {
                o00 = fmaxf(o00, 0.f); o01 = fmaxf(o01, 0.f);
                o10 = fmaxf(o10, 0.f); o11 = fmaxf(o11, 0.f);
            }
            if (NCHW_OUT) {
                out[( oc      * PO + py0)     * PO + px] = o00;
                out[((oc + 1) * PO + py0)     * PO + px] = o01;
                out[( oc      * PO + py0 + 1) * PO + px] = o10;
                out[((oc + 1) * PO + py0 + 1) * PO + px] = o11;
            } else {
                *(float2*)&out[((py0    ) * PO + px) * OCR + oc] = make_float2(o00, o01);
                *(float2*)&out[((py0 + 1) * PO + px) * OCR + oc] = make_float2(o10, o11);
            }
        }
    }
}

// ---------------------------------------------------------------------------
// First-layer conv: Cin=3 (padded to 4 in NHWC smem), H=64, conv+bias+act+pool.
// x is NCHW global. K per shift = 4 (one k4-frag), 9 shifts.
// ---------------------------------------------------------------------------
template <int OCR, int OCP, bool LEAKY, bool USE_DOM, bool NCHW_OUT>
__global__ __launch_bounds__(256) void conv_first_k(const float* __restrict__ x,
                                                    const float* __restrict__ W,
                                                    const float* __restrict__ bias,
                                                    const int*   __restrict__ dom,
                                                    float* __restrict__ out) {
    constexpr int PITCH = 272;                 // 66*4 padded to %32==16
    constexpr int NF = OCP / 8;
    constexpr int TX = 16, NST = 128, PO = 32;
    extern __shared__ float smem[];
    float* in_s = smem;                        // 66*272
    float* Bs   = smem + 66 * PITCH;           // 9*OCP*4
    float* b_s  = Bs + 9 * OCP * 4;            // OCP

    int b = blockIdx.x, tid = threadIdx.x;
    if (USE_DOM) { int d = *dom; W += d * OCR * 27; bias += d * OCR; }

    for (int i = tid; i < 66 * PITCH; i += 256) in_s[i] = 0.f;
    __syncthreads();
    const float* src = x + (size_t)b * 3 * 4096;
    for (int i = tid; i < 3 * 4096; i += 256) {
        int c = i >> 12, y = (i >> 6) & 63, xx = i & 63;
        in_s[(y + 1) * PITCH + (xx + 1) * 4 + c] = tf32r(src[i]);
    }
    for (int i = tid; i < 9 * OCP * 4; i += 256) {
        int s = i / (OCP * 4), oc = (i >> 2) % OCP, c = i & 3;
        Bs[i] = (oc < OCR && c < 3) ? tf32r(W[oc * 27 + c * 9 + s]) : 0.f;
    }
    if (tid < OCP) b_s[tid] = (tid < OCR) ? bias[tid] : 0.f;
    __syncthreads();

    int lane = tid & 31, warp = tid >> 5;
    int g = lane >> 2, t = lane & 3;
    const float* ap  = in_s + (g >> 2) * PITCH + (g & 3) * 4 + t;
    const float* bp0 = Bs + g * 4 + t;
    float* ob = out + (size_t)b * OCR * PO * PO;

    for (int s = warp; s < NST; s += 8) {
        int ty = (2 * s) / TX, tx0 = (2 * s) % TX;
        const float* a0p = ap + (ty * 4) * PITCH + (tx0 * 4) * 4;
        float acc[2][NF][4];
        #pragma unroll
        for (int j = 0; j < 2; j++)
            #pragma unroll
            for (int nf = 0; nf < NF; nf++)
                #pragma unroll
                for (int q = 0; q < 4; q++) acc[j][nf][q] = 0.f;

        #pragma unroll
        for (int ky = 0; ky < 3; ky++)
            #pragma unroll
            for (int kx = 0; kx < 3; kx++) {
                const float* q = a0p + ky * PITCH + kx * 4;
                uint32_t a00 = fbits(q[0]);
                uint32_t a01 = fbits(q[2 * PITCH]);
                uint32_t a10 = fbits(q[16]);
                uint32_t a11 = fbits(q[2 * PITCH + 16]);
                const float* bb = bp0 + (ky * 3 + kx) * OCP * 4;
                #pragma unroll
                for (int nf = 0; nf < NF; nf++) {
                    uint32_t bv = fbits(bb[nf * 32]);
                    mma4(acc[0][nf], a00, a01, bv);
                    mma4(acc[1][nf], a10, a11, bv);
                }
            }
        epilogue_tile<OCR, PO, LEAKY, NCHW_OUT>(acc[0], NF, ty, tx0,     g, t, b_s, ob);
        epilogue_tile<OCR, PO, LEAKY, NCHW_OUT>(acc[1], NF, ty, tx0 + 1, g, t, b_s, ob);
    }
}

// ---------------------------------------------------------------------------
// Mid conv: 36->36, input NHWC global [HH][HH][36], conv+bias+relu+pool.
// K=36 = 9 k4-frags per shift, 9 shifts. OCP=40 (NF=5).
// ---------------------------------------------------------------------------
template <int HH, bool NCHW_OUT>
__global__ __launch_bounds__(256) void conv_mid_k(const float* __restrict__ in,
                                                  const float* __restrict__ W,
                                                  const float* __restrict__ bias,
                                                  float* __restrict__ out) {
    constexpr int PITCH = (HH == 32) ? 1232 : 656;   // (HH+2)*36 padded to %32==16
    constexpr int ROWS = HH + 2;
    constexpr int TX = HH / 4, NST = TX * TX / 2, PO = HH / 2;
    constexpr int NF = 5;
    extern __shared__ float smem[];
    float* in_s = smem;                        // ROWS*PITCH
    float* Bs   = smem + ROWS * PITCH;         // 9*40*36
    float* b_s  = Bs + 9 * 40 * 36;

    int b = blockIdx.x, tid = threadIdx.x;
    for (int i = tid; i < ROWS * PITCH; i += 256) in_s[i] = 0.f;
    __syncthreads();
    const float* src = in + (size_t)b * HH * HH * 36;
    for (int i = tid; i < HH * HH * 36; i += 256) {
        int p = i / 36, c = i % 36;
        int y = p / HH, xx = p % HH;
        in_s[(y + 1) * PITCH + (xx + 1) * 36 + c] = tf32r(src[i]);
    }
    for (int i = tid; i < 9 * 40 * 36; i += 256) {
        int s = i / 1440, oc = (i / 36) % 40, ic = i % 36;
        Bs[i] = (oc < 36) ? tf32r(W[oc * 324 + ic * 9 + s]) : 0.f;
    }
    if (tid < 40) b_s[tid] = (tid < 36) ? bias[tid] : 0.f;
    __syncthreads();

    int lane = tid & 31, warp = tid >> 5;
    int g = lane >> 2, t = lane & 3;
    const float* ap  = in_s + (g >> 2) * PITCH + (g & 3) * 36 + t;
    const float* bp0 = Bs + g * 36 + t;
    float* ob = out + (size_t)b * 36 * PO * PO;

    for (int s = warp; s < NST; s += 8) {
        int ty = (2 * s) / TX, tx0 = (2 * s) % TX;
        const float* a0p = ap + (ty * 4) * PITCH + (tx0 * 4) * 36;
        float acc[2][NF][4];
        #pragma unroll
        for (int j = 0; j < 2; j++)
            #pragma unroll
            for (int nf = 0; nf < NF; nf++)
                #pragma unroll
                for (int q = 0; q < 4; q++) acc[j][nf][q] = 0.f;

        #pragma unroll 1
        for (int sh = 0; sh < 9; sh++) {
            int ky = sh / 3, kx = sh % 3;
            const float* q0 = a0p + ky * PITCH + kx * 36;
            const float* bb = bp0 + sh * 1440;
            #pragma unroll
            for (int k4 = 0; k4 < 9; k4++) {
                const float* q = q0 + k4 * 4;
                uint32_t a00 = fbits(q[0]);
                uint32_t a01 = fbits(q[2 * PITCH]);
                uint32_t a10 = fbits(q[144]);
                uint32_t a11 = fbits(q[2 * PITCH + 144]);
                #pragma unroll
                for (int nf = 0; nf < NF; nf++) {
                    uint32_t bv = fbits(bb[nf * 288 + k4 * 4]);
                    mma4(acc[0][nf], a00, a01, bv);
                    mma4(acc[1][nf], a10, a11, bv);
                }
            }
        }
        epilogue_tile<36, PO, false, NCHW_OUT>(acc[0], NF, ty, tx0,     g, t, b_s, ob);
        epilogue_tile<36, PO, false, NCHW_OUT>(acc[1], NF, ty, tx0 + 1, g, t, b_s, ob);
    }
}

// ---------------------------------------------------------------------------
// Batched FC (fp32, full precision): 16 samples/block, W staged in SMEM.
// ---------------------------------------------------------------------------
template <int K, int KC, bool RELU, bool USE_DOM>
__global__ __launch_bounds__(256) void fc_batch_k(const float* __restrict__ in,
                                                  const float* __restrict__ W,
                                                  const float* __restrict__ bias,
                                                  const int*   __restrict__ dom,
                                                  float* __restrict__ out) {
    extern __shared__ float ws[];
    if (USE_DOM) { int d = *dom; W += (size_t)d * 12 * K; bias += d * 12; }
    int tid = threadIdx.x, lane = tid & 31, l16 = lane & 15;
    int s = (tid >> 5) * 2 + (lane >> 4);
    const float* xp = in + ((size_t)blockIdx.x * 16 + s) * K;

    float acc[12];
    #pragma unroll
    for (int o = 0; o < 12; o++) acc[o] = 0.f;

    for (int kc0 = 0; kc0 < K; kc0 += KC) {
        __syncthreads();
        for (int i = tid; i < 12 * KC; i += 256) {
            int o = i / KC, k = i % KC;
            ws[i] = W[(size_t)o * K + kc0 + k];
        }
        __syncthreads();
        constexpr int NI = KC / 64;
        #pragma unroll 4
        for (int i = 0; i < NI; i++) {
            int k4 = l16 + i * 16;
            float4 xa = ((const float4*)(xp + kc0))[k4];
            #pragma unroll
            for (int o = 0; o < 12; o++) {
                float4 wa = ((const float4*)(ws + o * KC))[k4];
                acc[o] = fmaf(xa.x, wa.x, fmaf(xa.y, wa.y,
                          fmaf(xa.z, wa.z, fmaf(xa.w, wa.w, acc[o]))));
            }
        }
    }
    #pragma unroll
    for (int o = 0; o < 12; o++) {
        #pragma unroll
        for (int off = 8; off; off >>= 1)
            acc[o] += __shfl_down_sync(0xffffffffu, acc[o], off, 16);
    }
    if (l16 == 0) {
        size_t sg = (size_t)blockIdx.x * 16 + s;
        #pragma unroll
        for (int o = 0; o < 12; o++) {
            float v = acc[o] + bias[o];
            out[sg * 12 + o] = RELU ? fmaxf(v, 0.f) : v;
        }
    }
}

// ---------------------------------------------------------------------------
// Per-sample task-routed heads.
// ---------------------------------------------------------------------------
__global__ void heads_k(const float* __restrict__ h, const float* __restrict__ p,
                        const int* __restrict__ tt,
                        const float* __restrict__ W1, const float* __restrict__ b1,
                        const float* __restrict__ W2, const float* __restrict__ b2,
                        const float* __restrict__ W3, const float* __restrict__ b3,
                        float* __restrict__ out) {
    int bi = blockIdx.x * blockDim.x + threadIdx.x;
    if (bi >= 1024) return;
    int t = tt[bi];
    float x[24];
    #pragma unroll
    for (int i = 0; i < 12; i++) { x[i] = h[bi * 12 + i]; x[12 + i] = p[bi * 12 + i]; }
    float h1[28];
    const float* w1 = W1 + t * 28 * 24;
    #pragma unroll
    for (int i = 0; i < 28; i++) {
        float s = b1[t * 28 + i];
        #pragma unroll
        for (int j = 0; j < 24; j++) s = fmaf(w1[i * 24 + j], x[j], s);
        h1[i] = fmaxf(s, 0.f);
    }
    float h2[14];
    const float* w2 = W2 + t * 14 * 28;
    #pragma unroll
    for (int i = 0; i < 14; i++) {
        float s = b2[t * 14 + i];
        #pragma unroll
        for (int j = 0; j < 28; j++) s = fmaf(w2[i * 28 + j], h1[j], s);
        h2[i] = fmaxf(s, 0.f);
    }
    const float* w3 = W3 + t * 5 * 14;
    #pragma unroll
    for (int i = 0; i < 5; i++) {
        float s = b3[t * 5 + i];
        #pragma unroll
        for (int j = 0; j < 14; j++) s = fmaf(w3[i * 14 + j], h2[j], s);
        out[bi * 5 + i] = s;
    }
}

// ---------------------------------------------------------------------------
// Launch
// ---------------------------------------------------------------------------
extern "C" void kernel_launch(void* const* d_in, const int* in_sizes, int n_in,
                              void* d_out, int out_size) {
    const float* x_s      = (const float*)d_in[0];
    const float* x_p      = (const float*)d_in[1];
    const int*   tt       = (const int*)  d_in[2];
    const int*   dom      = (const int*)  d_in[3];
    const float* Ws_in_W  = (const float*)d_in[4];
    const float* Ws_in_b  = (const float*)d_in[5];
    const float* Ws_hid_W = (const float*)d_in[6];
    const float* Ws_hid_b = (const float*)d_in[7];
    const float* Ws_fc_W  = (const float*)d_in[8];
    const float* Ws_fc_b  = (const float*)d_in[9];
    const float* Pc_W     = (const float*)d_in[10];
    const float* Pc_b     = (const float*)d_in[11];
    const float* Pl_W     = (const float*)d_in[12];
    const float* Pl_b     = (const float*)d_in[13];
    const float* H1W      = (const float*)d_in[14];
    const float* H1b      = (const float*)d_in[15];
    const float* H2W      = (const float*)d_in[16];
    const float* H2b      = (const float*)d_in[17];
    const float* H3W      = (const float*)d_in[18];
    const float* H3b      = (const float*)d_in[19];
    float* out = (float*)d_out;

    float *s1, *s2, *s3, *hb, *p1, *pf;
    cudaGetSymbolAddress((void**)&s1, g_s1);
    cudaGetSymbolAddress((void**)&s2, g_s2);
    cudaGetSymbolAddress((void**)&s3, g_s3);
    cudaGetSymbolAddress((void**)&hb, g_h);
    cudaGetSymbolAddress((void**)&p1, g_p1);
    cudaGetSymbolAddress((void**)&pf, g_pf);

    const int SM_C1 = (66 * 272 + 9 * 40 * 4 + 40) * 4;          // 77728
    const int SM_CP = (66 * 272 + 9 * 16 * 4 + 16) * 4;          // 74176
    const int SM_C2 = (34 * 1232 + 9 * 40 * 36 + 40) * 4;        // 219552
    const int SM_C3 = (18 * 656  + 9 * 40 * 36 + 40) * 4;        // 99232
    const int SM_FCS = 12 * 2304 * 4;                            // 110592
    const int SM_FCP = 12 * 2048 * 4;                            // 98304

    cudaFuncSetAttribute((const void*)conv_first_k<36, 40, false, false, false>,
                         cudaFuncAttributeMaxDynamicSharedMemorySize, SM_C1);
    cudaFuncSetAttribute((const void*)conv_first_k<12, 16, true, true, true>,
                         cudaFuncAttributeMaxDynamicSharedMemorySize, SM_CP);
    cudaFuncSetAttribute((const void*)conv_mid_k<32, false>,
                         cudaFuncAttributeMaxDynamicSharedMemorySize, SM_C2);
    cudaFuncSetAttribute((const void*)conv_mid_k<16, true>,
                         cudaFuncAttributeMaxDynamicSharedMemorySize, SM_C3);
    cudaFuncSetAttribute((const void*)fc_batch_k<2304, 2304, true, false>,
                         cudaFuncAttributeMaxDynamicSharedMemorySize, SM_FCS);
    cudaFuncSetAttribute((const void*)fc_batch_k<12288, 2048, false, true>,
                         cudaFuncAttributeMaxDynamicSharedMemorySize, SM_FCP);

    // Shared branch: conv1 (NHWC out) -> conv2 (NHWC out) -> conv3 (NCHW out) -> fc
    conv_first_k<36, 40, false, false, false><<<1024, 256, SM_C1>>>(x_s, Ws_in_W, Ws_in_b, nullptr, s1);
    conv_mid_k<32, false><<<1024, 256, SM_C2>>>(s1, Ws_hid_W, Ws_hid_b, s2);
    conv_mid_k<16, true><<<1024, 256, SM_C3>>>(s2, Ws_hid_W, Ws_hid_b, s3);
    // Private branch: conv (NCHW out) -> fc
    conv_first_k<12, 16, true, true, true><<<1024, 256, SM_CP>>>(x_p, Pc_W, Pc_b, dom, p1);
    fc_batch_k<2304, 2304, true, false><<<64, 256, SM_FCS>>>(s3, Ws_fc_W, Ws_fc_b, nullptr, hb);
    fc_batch_k<12288, 2048, false, true><<<64, 256, SM_FCP>>>(p1, Pl_W, Pl_b, dom, pf);
    heads_k<<<4, 256>>>(hb, pf, tt, H1W, H1b, H2W, H2b, H3W, H3b, out);
}

// round 10
// speedup vs baseline: 1.5169x; 1.5169x over previous
#include <cuda_runtime.h>
#include <cuda_bf16.h>
#include <cstdint>

// ---------------------------------------------------------------------------
// bf16 helpers
// ---------------------------------------------------------------------------
__device__ __forceinline__ uint32_t pkbf(float lo, float hi) {
    uint32_t r; asm("cvt.rn.bf16x2.f32 %0,%1,%2;" : "=r"(r) : "f"(hi), "f"(lo));
    return r;
}
__device__ __forceinline__ void mma16(float* c, uint32_t a0, uint32_t a1,
                                      uint32_t a2, uint32_t a3,
                                      uint32_t b0, uint32_t b1) {
    asm("mma.sync.aligned.m16n8k16.row.col.f32.bf16.bf16.f32 "
        "{%0,%1,%2,%3},{%4,%5,%6,%7},{%8,%9},{%0,%1,%2,%3};"
        : "+f"(c[0]), "+f"(c[1]), "+f"(c[2]), "+f"(c[3])
        : "r"(a0), "r"(a1), "r"(a2), "r"(a3), "r"(b0), "r"(b1));
}

// ---------------------------------------------------------------------------
// Scratch
// ---------------------------------------------------------------------------
__device__ __nv_bfloat16 g_s1[1024 * 32 * 32 * 36];  // conv1 out, NHWC bf16
__device__ __nv_bfloat16 g_s2[1024 * 16 * 16 * 36];  // conv2 out, NHWC bf16
__device__ float         g_s3[1024 * 36 * 8 * 8];    // conv3 out, NCHW f32
__device__ float         g_h [1024 * 12];
__device__ __nv_bfloat16 g_p1[1024 * 12 * 32 * 32];  // private conv, NCHW bf16
__device__ float         g_pf[1024 * 12];

// ---------------------------------------------------------------------------
// Epilogue: in-fragment 2x2 maxpool via shfl, bias+act, store.
// C frag: c0=(row g, col 2t), c1=(g,2t+1), c2=(g+8,2t), c3=(g+8,2t+1);
// row r -> (dy = (r&7)>>2 + 2*(r>>3), dx = r&3).
// MODE 0: NHWC bf16 (paired u32); MODE 1: NCHW f32; MODE 2: NCHW bf16.
// ---------------------------------------------------------------------------
template <int MODE, int OCR, int PO, bool LEAKY>
__device__ __forceinline__ void epi(const float acc[][4], int NF,
                                    int ty, int tx, int g, int t,
                                    const float* b_s, void* outp) {
    for (int nf = 0; nf < NF; nf++) {
        float v0 = acc[nf][0], v1 = acc[nf][1], v2 = acc[nf][2], v3 = acc[nf][3];
        v0 = fmaxf(v0, __shfl_xor_sync(0xffffffffu, v0, 4));
        v1 = fmaxf(v1, __shfl_xor_sync(0xffffffffu, v1, 4));
        v2 = fmaxf(v2, __shfl_xor_sync(0xffffffffu, v2, 4));
        v3 = fmaxf(v3, __shfl_xor_sync(0xffffffffu, v3, 4));
        v0 = fmaxf(v0, __shfl_xor_sync(0xffffffffu, v0, 16));
        v1 = fmaxf(v1, __shfl_xor_sync(0xffffffffu, v1, 16));
        v2 = fmaxf(v2, __shfl_xor_sync(0xffffffffu, v2, 16));
        v3 = fmaxf(v3, __shfl_xor_sync(0xffffffffu, v3, 16));
        int oc = nf * 8 + 2 * t;
        if (((g & 1) == 0) && (g < 4) && oc < OCR) {
            int px  = tx * 2 + (g >> 1);
            int py0 = ty * 2;
            float b0 = b_s[oc], b1 = b_s[oc + 1];
            float o00 = v0 + b0, o01 = v1 + b1, o10 = v2 + b0, o11 = v3 + b1;
            if (LEAKY) {
                o00 = o00 > 0.f ? o00 : 0.001f * o00;
                o01 = o01 > 0.f ? o01 : 0.001f * o01;
                o10 = o10 > 0.f ? o10 : 0.001f * o10;
                o11 = o11 > 0.f ? o11 : 0.001f * o11;
            } else {
                o00 = fmaxf(o00, 0.f); o01 = fmaxf(o01, 0.f);
                o10 = fmaxf(o10, 0.f); o11 = fmaxf(o11, 0.f);
            }
            if (MODE == 0) {
                uint32_t* o32 = (uint32_t*)outp;
                constexpr int ST = OCR / 2;
                o32[( py0      * PO + px) * ST + (oc >> 1)] = pkbf(o00, o01);
                o32[((py0 + 1) * PO + px) * ST + (oc >> 1)] = pkbf(o10, o11);
            } else if (MODE == 1) {
                float* of = (float*)outp;
                of[( oc      * PO + py0)     * PO + px] = o00;
                of[((oc + 1) * PO + py0)     * PO + px] = o01;
                of[( oc      * PO + py0 + 1) * PO + px] = o10;
                of[((oc + 1) * PO + py0 + 1) * PO + px] = o11;
            } else {
                __nv_bfloat16* ob = (__nv_bfloat16*)outp;
                ob[( oc      * PO + py0)     * PO + px] = __float2bfloat16_rn(o00);
                ob[((oc + 1) * PO + py0)     * PO + px] = __float2bfloat16_rn(o01);
                ob[( oc      * PO + py0 + 1) * PO + px] = __float2bfloat16_rn(o10);
                ob[((oc + 1) * PO + py0 + 1) * PO + px] = __float2bfloat16_rn(o11);
            }
        }
    }
}

// ---------------------------------------------------------------------------
// First conv: Cin=3 (padded to 4ch NHWC bf16), H=64, conv+bias+act+pool.
// K=16 per ky = 4 pixels x 4ch (kx=3 pixel & ch=3 weights are zero).
// ---------------------------------------------------------------------------
template <int OCR, int OCP, bool LEAKY, bool USE_DOM, int MODE>
__global__ __launch_bounds__(256) void conv_first_k(const float* __restrict__ x,
                                                    const float* __restrict__ W,
                                                    const float* __restrict__ bias,
                                                    const int*   __restrict__ dom,
                                                    void* __restrict__ outv) {
    constexpr int P32 = 144;                   // u32/row; 144%32==16 -> A conflict-free
    constexpr int NF  = OCP / 8;
    constexpr int SB  = 40;                    // B oc-stride (t*40+g) -> bank-free
    extern __shared__ uint32_t sm32[];
    uint32_t* in32 = sm32;                     // 66*144
    uint32_t* B32  = sm32 + 66 * P32;          // [3 ky][8 kpair][SB oc]
    float*    b_s  = (float*)(B32 + 3 * 8 * SB);

    int b = blockIdx.x, tid = threadIdx.x;
    if (USE_DOM) { int d = *dom; W += d * OCR * 27; bias += d * OCR; }

    for (int i = tid; i < 66 * P32; i += 256) in32[i] = 0u;
    __syncthreads();
    const float* src = x + (size_t)b * 3 * 4096;
    for (int p = tid; p < 4096; p += 256) {
        int y = p >> 6, xx = p & 63;
        int dst = (y + 1) * P32 + (xx + 1) * 2;
        in32[dst]     = pkbf(src[p], src[4096 + p]);
        in32[dst + 1] = pkbf(src[8192 + p], 0.f);
    }
    for (int i = tid; i < 3 * 8 * SB; i += 256) {
        int ky = i / (8 * SB), rem = i - ky * 8 * SB;
        int j = rem / SB, oc = rem % SB;
        int kx = j >> 1, ch0 = (j & 1) * 2;    // k-pair j -> pixel kx, channels ch0,ch0+1
        float w0 = 0.f, w1 = 0.f;
        if (oc < OCR && kx < 3) {
            w0 = W[oc * 27 + ch0 * 9 + ky * 3 + kx];
            if (ch0 + 1 < 3) w1 = W[oc * 27 + (ch0 + 1) * 9 + ky * 3 + kx];
        }
        B32[i] = pkbf(w0, w1);
    }
    if (tid < OCP) b_s[tid] = (tid < OCR) ? bias[tid] : 0.f;
    __syncthreads();

    int lane = tid & 31, warp = tid >> 5;
    int g = lane >> 2, t = lane & 3;
    int dy = g >> 2, dxl = g & 3;
    void* outp;
    if (MODE == 0)      outp = (void*)((uint32_t*)outv + (size_t)b * 32 * 32 * (OCR / 2));
    else                outp = (void*)((__nv_bfloat16*)outv + (size_t)b * OCR * 32 * 32);

    for (int s = warp; s < 128; s += 8) {
        int ty = s >> 3, tx0 = (2 * s) & 15;
        const uint32_t* ab = in32 + (ty * 4 + dy) * P32 + (tx0 * 4 + dxl) * 2 + t;
        float acc[2][NF][4];
        #pragma unroll
        for (int j = 0; j < 2; j++)
            #pragma unroll
            for (int nf = 0; nf < NF; nf++)
                #pragma unroll
                for (int q = 0; q < 4; q++) acc[j][nf][q] = 0.f;

        #pragma unroll
        for (int ky = 0; ky < 3; ky++) {
            const uint32_t* ap = ab + ky * P32;
            uint32_t a00 = ap[0], a01 = ap[2 * P32],     a02 = ap[4],  a03 = ap[2 * P32 + 4];
            uint32_t a10 = ap[8], a11 = ap[2 * P32 + 8], a12 = ap[12], a13 = ap[2 * P32 + 12];
            const uint32_t* bp = B32 + ky * 8 * SB + t * SB + g;
            #pragma unroll
            for (int nf = 0; nf < NF; nf++) {
                uint32_t b0 = bp[nf * 8], b1 = bp[4 * SB + nf * 8];
                mma16(acc[0][nf], a00, a01, a02, a03, b0, b1);
                mma16(acc[1][nf], a10, a11, a12, a13, b0, b1);
            }
        }
        epi<MODE, OCR, 32, LEAKY>(acc[0], NF, ty, tx0,     g, t, b_s, outp);
        epi<MODE, OCR, 32, LEAKY>(acc[1], NF, ty, tx0 + 1, g, t, b_s, outp);
    }
}

// ---------------------------------------------------------------------------
// Mid conv: 36->36, NHWC bf16 in, conv+bias+relu+pool.
// Per ky: K-run = 3 pixels x 36ch = 108 slots -> 7 k16 frags (tail zero-weight;
// over-read 4th pixel is zeroed padding). B [ky][56 kpair][40 oc]: bank-free.
// ---------------------------------------------------------------------------
template <int HH, int MODE>
__global__ __launch_bounds__(256) void conv_mid_k(const __nv_bfloat16* __restrict__ in,
                                                  const float* __restrict__ W,
                                                  const float* __restrict__ bias,
                                                  void* __restrict__ outv) {
    constexpr int P32  = (HH == 32) ? 632 : 344;   // u32/row
    constexpr int ROWS = HH + 2;
    constexpr int TX   = HH / 4;
    constexpr int NST  = HH * HH / 32;
    constexpr int PO   = HH / 2;
    extern __shared__ uint32_t sm32[];
    uint32_t* in32 = sm32;                         // ROWS*P32
    uint32_t* B32  = sm32 + ROWS * P32;            // 3*56*40 = 6720
    float*    b_s  = (float*)(B32 + 6720);

    int b = blockIdx.x, tid = threadIdx.x;
    for (int i = tid; i < ROWS * P32; i += 256) in32[i] = 0u;
    __syncthreads();

    const uint2* src2 = (const uint2*)(in + (size_t)b * HH * HH * 36);
    uint2* dst2 = (uint2*)in32;
    for (int i = tid; i < HH * HH * 9; i += 256) {
        int p = i / 9, q = i - p * 9;
        int y = p / HH, xx = p % HH;
        dst2[(((y + 1) * P32 + (xx + 1) * 18) >> 1) + q] = src2[i];
    }
    for (int i = tid; i < 6720; i += 256) {
        int ky = i / 2240, rem = i - ky * 2240;
        int j = rem / 40, oc = rem % 40;
        int c = 2 * j, p = c / 36, ch = c - 36 * p;  // k slot = pix*36+ch
        float w0 = 0.f, w1 = 0.f;
        if (p < 3 && oc < 36) {
            w0 = W[oc * 324 + ch * 9 + ky * 3 + p];
            w1 = W[oc * 324 + (ch + 1) * 9 + ky * 3 + p];
        }
        B32[i] = pkbf(w0, w1);
    }
    if (tid < 40) b_s[tid] = (tid < 36) ? bias[tid] : 0.f;
    __syncthreads();

    int lane = tid & 31, warp = tid >> 5;
    int g = lane >> 2, t = lane & 3;
    int dy = g >> 2, dxl = g & 3;
    void* outp;
    if (MODE == 0) outp = (void*)((uint32_t*)outv + (size_t)b * PO * PO * 18);
    else           outp = (void*)((float*)outv + (size_t)b * 36 * PO * PO);

    for (int s = warp; s < NST; s += 8) {
        int ty = (2 * s) / TX, tx0 = (2 * s) % TX;
        const uint32_t* ab = in32 + (ty * 4 + dy) * P32 + (tx0 * 4 + dxl) * 18 + t;
        float acc[2][5][4];
        #pragma unroll
        for (int j = 0; j < 2; j++)
            #pragma unroll
            for (int nf = 0; nf < 5; nf++)
                #pragma unroll
                for (int q = 0; q < 4; q++) acc[j][nf][q] = 0.f;

        #pragma unroll
        for (int ky = 0; ky < 3; ky++) {
            #pragma unroll
            for (int f = 0; f < 7; f++) {
                const uint32_t* ap = ab + ky * P32 + f * 8;
                uint32_t a00 = ap[0],  a01 = ap[2 * P32],      a02 = ap[4],  a03 = ap[2 * P32 + 4];
                uint32_t a10 = ap[72], a11 = ap[2 * P32 + 72], a12 = ap[76], a13 = ap[2 * P32 + 76];
                const uint32_t* bp  = B32 + ky * 2240 + (f * 8 + t) * 40 + g;
                const uint32_t* bp1 = bp + 160;
                #pragma unroll
                for (int nf = 0; nf < 5; nf++) {
                    uint32_t b0 = bp[nf * 8], b1 = bp1[nf * 8];
                    mma16(acc[0][nf], a00, a01, a02, a03, b0, b1);
                    mma16(acc[1][nf], a10, a11, a12, a13, b0, b1);
                }
            }
        }
        epi<MODE, 36, PO, false>(acc[0], 5, ty, tx0,     g, t, b_s, outp);
        epi<MODE, 36, PO, false>(acc[1], 5, ty, tx0 + 1, g, t, b_s, outp);
    }
}

// ---------------------------------------------------------------------------
// Batched FC (f32 input): 16 samples/block, W staged in SMEM.
// ---------------------------------------------------------------------------
template <int K, int KC, bool RELU>
__global__ __launch_bounds__(256) void fc_batch_k(const float* __restrict__ in,
                                                  const float* __restrict__ W,
                                                  const float* __restrict__ bias,
                                                  float* __restrict__ out) {
    extern __shared__ float ws[];
    int tid = threadIdx.x, lane = tid & 31, l16 = lane & 15;
    int s = (tid >> 5) * 2 + (lane >> 4);
    const float* xp = in + ((size_t)blockIdx.x * 16 + s) * K;
    float acc[12];
    #pragma unroll
    for (int o = 0; o < 12; o++) acc[o] = 0.f;

    for (int kc0 = 0; kc0 < K; kc0 += KC) {
        __syncthreads();
        for (int i = tid; i < 12 * KC; i += 256)
            ws[i] = W[(size_t)(i / KC) * K + kc0 + (i % KC)];
        __syncthreads();
        constexpr int NI = KC / 64;
        #pragma unroll 4
        for (int i = 0; i < NI; i++) {
            int k4 = l16 + i * 16;
            float4 xa = ((const float4*)(xp + kc0))[k4];
            #pragma unroll
            for (int o = 0; o < 12; o++) {
                float4 wa = ((const float4*)(ws + o * KC))[k4];
                acc[o] = fmaf(xa.x, wa.x, fmaf(xa.y, wa.y,
                          fmaf(xa.z, wa.z, fmaf(xa.w, wa.w, acc[o]))));
            }
        }
    }
    #pragma unroll
    for (int o = 0; o < 12; o++)
        #pragma unroll
        for (int off = 8; off; off >>= 1)
            acc[o] += __shfl_down_sync(0xffffffffu, acc[o], off, 16);
    if (l16 == 0) {
        size_t sg = (size_t)blockIdx.x * 16 + s;
        #pragma unroll
        for (int o = 0; o < 12; o++) {
            float v = acc[o] + bias[o];
            out[sg * 12 + o] = RELU ? fmaxf(v, 0.f) : v;
        }
    }
}

// ---------------------------------------------------------------------------
// Private FC: bf16 input [B,12288] @ Pl_W[dom][12,12288]^T + Pl_b[dom].
// ---------------------------------------------------------------------------
template <int K, int KC>
__global__ __launch_bounds__(256) void fc_priv_k(const __nv_bfloat16* __restrict__ in,
                                                 const float* __restrict__ W,
                                                 const float* __restrict__ bias,
                                                 const int*   __restrict__ dom,
                                                 float* __restrict__ out) {
    extern __shared__ float ws[];
    int d = *dom;
    W += (size_t)d * 12 * K; bias += d * 12;
    int tid = threadIdx.x, lane = tid & 31, l16 = lane & 15;
    int s = (tid >> 5) * 2 + (lane >> 4);
    const __nv_bfloat16* xp = in + ((size_t)blockIdx.x * 16 + s) * K;
    float acc[12];
    #pragma unroll
    for (int o = 0; o < 12; o++) acc[o] = 0.f;

    for (int kc0 = 0; kc0 < K; kc0 += KC) {
        __syncthreads();
        for (int i = tid; i < 12 * KC; i += 256)
            ws[i] = W[(size_t)(i / KC) * K + kc0 + (i % KC)];
        __syncthreads();
        constexpr int NI = KC / 64;
        #pragma unroll 4
        for (int i = 0; i < NI; i++) {
            int k4 = l16 + i * 16;
            uint2 xa = ((const uint2*)(xp + kc0))[k4];   // 4 bf16
            float2 x01 = __bfloat1622float2(*(const __nv_bfloat162*)&xa.x);
            float2 x23 = __bfloat1622float2(*(const __nv_bfloat162*)&xa.y);
            #pragma unroll
            for (int o = 0; o < 12; o++) {
                float4 wa = ((const float4*)(ws + o * KC))[k4];
                acc[o] = fmaf(x01.x, wa.x, fmaf(x01.y, wa.y,
                          fmaf(x23.x, wa.z, fmaf(x23.y, wa.w, acc[o]))));
            }
        }
    }
    #pragma unroll
    for (int o = 0; o < 12; o++)
        #pragma unroll
        for (int off = 8; off; off >>= 1)
            acc[o] += __shfl_down_sync(0xffffffffu, acc[o], off, 16);
    if (l16 == 0) {
        size_t sg = (size_t)blockIdx.x * 16 + s;
        #pragma unroll
        for (int o = 0; o < 12; o++)
            out[sg * 12 + o] = acc[o] + bias[o];
    }
}

// ---------------------------------------------------------------------------
// Per-sample task-routed heads.
// ---------------------------------------------------------------------------
__global__ void heads_k(const float* __restrict__ h, const float* __restrict__ p,
                        const int* __restrict__ tt,
                        const float* __restrict__ W1, const float* __restrict__ b1,
                        const float* __restrict__ W2, const float* __restrict__ b2,
                        const float* __restrict__ W3, const float* __restrict__ b3,
                        float* __restrict__ out) {
    int bi = blockIdx.x * blockDim.x + threadIdx.x;
    if (bi >= 1024) return;
    int t = tt[bi];
    float x[24];
    #pragma unroll
    for (int i = 0; i < 12; i++) { x[i] = h[bi * 12 + i]; x[12 + i] = p[bi * 12 + i]; }
    float h1[28];
    const float* w1 = W1 + t * 28 * 24;
    #pragma unroll
    for (int i = 0; i < 28; i++) {
        float s = b1[t * 28 + i];
        #pragma unroll
        for (int j = 0; j < 24; j++) s = fmaf(w1[i * 24 + j], x[j], s);
        h1[i] = fmaxf(s, 0.f);
    }
    float h2[14];
    const float* w2 = W2 + t * 14 * 28;
    #pragma unroll
    for (int i = 0; i < 14; i++) {
        float s = b2[t * 14 + i];
        #pragma unroll
        for (int j = 0; j < 28; j++) s = fmaf(w2[i * 28 + j], h1[j], s);
        h2[i] = fmaxf(s, 0.f);
    }
    const float* w3 = W3 + t * 5 * 14;
    #pragma unroll
    for (int i = 0; i < 5; i++) {
        float s = b3[t * 5 + i];
        #pragma unroll
        for (int j = 0; j < 14; j++) s = fmaf(w3[i * 14 + j], h2[j], s);
        out[bi * 5 + i] = s;
    }
}

// ---------------------------------------------------------------------------
// Launch
// ---------------------------------------------------------------------------
extern "C" void kernel_launch(void* const* d_in, const int* in_sizes, int n_in,
                              void* d_out, int out_size) {
    const float* x_s      = (const float*)d_in[0];
    const float* x_p      = (const float*)d_in[1];
    const int*   tt       = (const int*)  d_in[2];
    const int*   dom      = (const int*)  d_in[3];
    const float* Ws_in_W  = (const float*)d_in[4];
    const float* Ws_in_b  = (const float*)d_in[5];
    const float* Ws_hid_W = (const float*)d_in[6];
    const float* Ws_hid_b = (const float*)d_in[7];
    const float* Ws_fc_W  = (const float*)d_in[8];
    const float* Ws_fc_b  = (const float*)d_in[9];
    const float* Pc_W     = (const float*)d_in[10];
    const float* Pc_b     = (const float*)d_in[11];
    const float* Pl_W     = (const float*)d_in[12];
    const float* Pl_b     = (const float*)d_in[13];
    const float* H1W      = (const float*)d_in[14];
    const float* H1b      = (const float*)d_in[15];
    const float* H2W      = (const float*)d_in[16];
    const float* H2b      = (const float*)d_in[17];
    const float* H3W      = (const float*)d_in[18];
    const float* H3b      = (const float*)d_in[19];
    float* out = (float*)d_out;

    __nv_bfloat16 *s1, *s2, *p1;
    float *s3, *hb, *pf;
    cudaGetSymbolAddress((void**)&s1, g_s1);
    cudaGetSymbolAddress((void**)&s2, g_s2);
    cudaGetSymbolAddress((void**)&s3, g_s3);
    cudaGetSymbolAddress((void**)&hb, g_h);
    cudaGetSymbolAddress((void**)&p1, g_p1);
    cudaGetSymbolAddress((void**)&pf, g_pf);

    const int SM_CF  = (66 * 144 + 3 * 8 * 40 + 40) * 4;     // 42016
    const int SM_M32 = (34 * 632 + 6720 + 40) * 4;           // 112992
    const int SM_M16 = (18 * 344 + 6720 + 40) * 4;           // 51808
    const int SM_FCS = 12 * 2304 * 4;                        // 110592
    const int SM_FCP = 12 * 2048 * 4;                        // 98304

    cudaFuncSetAttribute((const void*)conv_first_k<36, 40, false, false, 0>,
                         cudaFuncAttributeMaxDynamicSharedMemorySize, SM_CF);
    cudaFuncSetAttribute((const void*)conv_first_k<12, 16, true, true, 2>,
                         cudaFuncAttributeMaxDynamicSharedMemorySize, SM_CF);
    cudaFuncSetAttribute((const void*)conv_mid_k<32, 0>,
                         cudaFuncAttributeMaxDynamicSharedMemorySize, SM_M32);
    cudaFuncSetAttribute((const void*)conv_mid_k<16, 1>,
                         cudaFuncAttributeMaxDynamicSharedMemorySize, SM_M16);
    cudaFuncSetAttribute((const void*)fc_batch_k<2304, 2304, true>,
                         cudaFuncAttributeMaxDynamicSharedMemorySize, SM_FCS);
    cudaFuncSetAttribute((const void*)fc_priv_k<12288, 2048>,
                         cudaFuncAttributeMaxDynamicSharedMemorySize, SM_FCP);

    // Shared branch: conv1 (NHWC bf16) -> conv2 (NHWC bf16) -> conv3 (NCHW f32) -> fc
    conv_first_k<36, 40, false, false, 0><<<1024, 256, SM_CF>>>(x_s, Ws_in_W, Ws_in_b, nullptr, s1);
    conv_mid_k<32, 0><<<1024, 256, SM_M32>>>(s1, Ws_hid_W, Ws_hid_b, s2);
    conv_mid_k<16, 1><<<1024, 256, SM_M16>>>(s2, Ws_hid_W, Ws_hid_b, s3);
    // Private branch: conv (NCHW bf16) -> fc
    conv_first_k<12, 16, true, true, 2><<<1024, 256, SM_CF>>>(x_p, Pc_W, Pc_b, dom, p1);
    fc_batch_k<2304, 2304, true><<<64, 256, SM_FCS>>>(s3, Ws_fc_W, Ws_fc_b, hb);
    fc_priv_k<12288, 2048><<<64, 256, SM_FCP>>>(p1, Pl_W, Pl_b, dom, pf);
    heads_k<<<4, 256>>>(hb, pf, tt, H1W, H1b, H2W, H2b, H3W, H3b, out);
}

// round 11
// speedup vs baseline: 1.7130x; 1.1292x over previous
#include <cuda_runtime.h>
#include <cuda_bf16.h>
#include <cstdint>

// ---------------------------------------------------------------------------
// helpers
// ---------------------------------------------------------------------------
__device__ __forceinline__ uint32_t pkbf(float lo, float hi) {
    uint32_t r; asm("cvt.rn.bf16x2.f32 %0,%1,%2;" : "=r"(r) : "f"(hi), "f"(lo));
    return r;
}
__device__ __forceinline__ void mma16(float* c, uint32_t a0, uint32_t a1,
                                      uint32_t a2, uint32_t a3,
                                      uint32_t b0, uint32_t b1) {
    asm("mma.sync.aligned.m16n8k16.row.col.f32.bf16.bf16.f32 "
        "{%0,%1,%2,%3},{%4,%5,%6,%7},{%8,%9},{%0,%1,%2,%3};"
        : "+f"(c[0]), "+f"(c[1]), "+f"(c[2]), "+f"(c[3])
        : "r"(a0), "r"(a1), "r"(a2), "r"(a3), "r"(b0), "r"(b1));
}
__device__ __forceinline__ void ldsm4(uint32_t* a, uint32_t saddr) {
    asm volatile("ldmatrix.sync.aligned.m8n8.x4.shared.b16 {%0,%1,%2,%3},[%4];"
                 : "=r"(a[0]), "=r"(a[1]), "=r"(a[2]), "=r"(a[3]) : "r"(saddr));
}

// ---------------------------------------------------------------------------
// Scratch
// ---------------------------------------------------------------------------
__device__ __nv_bfloat16 g_s1[1024 * 32 * 32 * 36];  // conv1 out, NHWC bf16
__device__ __nv_bfloat16 g_s2[1024 * 16 * 16 * 36];  // conv2 out, NHWC bf16
__device__ float         g_s3[1024 * 36 * 8 * 8];    // conv3 out, NCHW f32
__device__ float         g_h [1024 * 12];
__device__ __nv_bfloat16 g_p1[1024 * 32 * 32 * 12];  // private conv, NHWC bf16
__device__ float         g_pf[1024 * 12];
__device__ float         g_pw[12 * 12288];           // Pl_W[dom] permuted to NHWC

// ---------------------------------------------------------------------------
// Epilogue: in-fragment 2x2 maxpool via shfl, bias+act, store.
// MODE 0: NHWC bf16 (u32 pairs); MODE 1: NCHW f32.
// ---------------------------------------------------------------------------
template <int MODE, int OCR, int PO, bool LEAKY>
__device__ __forceinline__ void epi(const float acc[][4], int NF,
                                    int ty, int tx, int g, int t,
                                    const float* b_s, void* outp) {
    for (int nf = 0; nf < NF; nf++) {
        float v0 = acc[nf][0], v1 = acc[nf][1], v2 = acc[nf][2], v3 = acc[nf][3];
        v0 = fmaxf(v0, __shfl_xor_sync(0xffffffffu, v0, 4));
        v1 = fmaxf(v1, __shfl_xor_sync(0xffffffffu, v1, 4));
        v2 = fmaxf(v2, __shfl_xor_sync(0xffffffffu, v2, 4));
        v3 = fmaxf(v3, __shfl_xor_sync(0xffffffffu, v3, 4));
        v0 = fmaxf(v0, __shfl_xor_sync(0xffffffffu, v0, 16));
        v1 = fmaxf(v1, __shfl_xor_sync(0xffffffffu, v1, 16));
        v2 = fmaxf(v2, __shfl_xor_sync(0xffffffffu, v2, 16));
        v3 = fmaxf(v3, __shfl_xor_sync(0xffffffffu, v3, 16));
        int oc = nf * 8 + 2 * t;
        if (((g & 1) == 0) && (g < 4) && oc < OCR) {
            int px  = tx * 2 + (g >> 1);
            int py0 = ty * 2;
            float b0 = b_s[oc], b1 = b_s[oc + 1];
            float o00 = v0 + b0, o01 = v1 + b1, o10 = v2 + b0, o11 = v3 + b1;
            if (LEAKY) {
                o00 = o00 > 0.f ? o00 : 0.001f * o00;
                o01 = o01 > 0.f ? o01 : 0.001f * o01;
                o10 = o10 > 0.f ? o10 : 0.001f * o10;
                o11 = o11 > 0.f ? o11 : 0.001f * o11;
            } else {
                o00 = fmaxf(o00, 0.f); o01 = fmaxf(o01, 0.f);
                o10 = fmaxf(o10, 0.f); o11 = fmaxf(o11, 0.f);
            }
            if (MODE == 0) {
                uint32_t* o32 = (uint32_t*)outp;
                constexpr int ST = OCR / 2;
                o32[( py0      * PO + px) * ST + (oc >> 1)] = pkbf(o00, o01);
                o32[((py0 + 1) * PO + px) * ST + (oc >> 1)] = pkbf(o10, o11);
            } else {
                float* of = (float*)outp;
                of[( oc      * PO + py0)     * PO + px] = o00;
                of[((oc + 1) * PO + py0)     * PO + px] = o01;
                of[( oc      * PO + py0 + 1) * PO + px] = o10;
                of[((oc + 1) * PO + py0 + 1) * PO + px] = o11;
            }
        }
    }
}

// ---------------------------------------------------------------------------
// First-conv body: Cin=3 (4ch-padded NHWC bf16), H=64, conv+bias+act+pool.
// NHWC out (MODE 0). Halo-only zeroing.
// ---------------------------------------------------------------------------
template <int OCR, int OCP, bool LEAKY, bool USE_DOM>
__device__ void conv_first_body(int b, const float* __restrict__ x,
                                const float* __restrict__ W,
                                const float* __restrict__ bias,
                                const int* __restrict__ dom,
                                uint32_t* __restrict__ outb) {
    constexpr int P32 = 144;
    constexpr int NF  = OCP / 8;
    constexpr int SB  = 40;
    extern __shared__ uint32_t sm32[];
    uint32_t* in32 = sm32;                     // 66*144
    uint32_t* B32  = sm32 + 66 * P32;          // 3*8*SB
    float*    b_s  = (float*)(B32 + 3 * 8 * SB);

    int tid = threadIdx.x;
    if (USE_DOM) { int d = *dom; W += d * OCR * 27; bias += d * OCR; }

    // halo-only zero: rows 0/65 full; rows 1..64 cols {0,1} U [130,144)
    for (int i = tid; i < 2 * P32; i += 256)
        in32[(i < P32 ? 0 : 65) * P32 + (i % P32)] = 0u;
    for (int i = tid; i < 64 * 16; i += 256) {
        int rr = i / 16 + 1, cc = i % 16;
        in32[rr * P32 + (cc < 2 ? cc : 128 + cc)] = 0u;
    }
    const float* src = x + (size_t)b * 3 * 4096;
    for (int p = tid; p < 4096; p += 256) {
        int y = p >> 6, xx = p & 63;
        int dst = (y + 1) * P32 + (xx + 1) * 2;
        in32[dst]     = pkbf(src[p], src[4096 + p]);
        in32[dst + 1] = pkbf(src[8192 + p], 0.f);
    }
    for (int i = tid; i < 3 * 8 * SB; i += 256) {
        int ky = i / (8 * SB), rem = i - ky * 8 * SB;
        int j = rem / SB, oc = rem % SB;
        int kx = j >> 1, ch0 = (j & 1) * 2;
        float w0 = 0.f, w1 = 0.f;
        if (oc < OCR && kx < 3) {
            w0 = W[oc * 27 + ch0 * 9 + ky * 3 + kx];
            if (ch0 + 1 < 3) w1 = W[oc * 27 + (ch0 + 1) * 9 + ky * 3 + kx];
        }
        B32[i] = pkbf(w0, w1);
    }
    if (tid < OCP) b_s[tid] = (tid < OCR) ? bias[tid] : 0.f;
    __syncthreads();

    int lane = tid & 31, warp = tid >> 5;
    int g = lane >> 2, t = lane & 3;
    int dy = g >> 2, dxl = g & 3;
    uint32_t* outp = outb + (size_t)b * 32 * 32 * (OCR / 2);

    for (int s = warp; s < 128; s += 8) {
        int ty = s >> 3, tx0 = (2 * s) & 15;
        const uint32_t* ab = in32 + (ty * 4 + dy) * P32 + (tx0 * 4 + dxl) * 2 + t;
        float acc[2][NF][4];
        #pragma unroll
        for (int j = 0; j < 2; j++)
            #pragma unroll
            for (int nf = 0; nf < NF; nf++)
                #pragma unroll
                for (int q = 0; q < 4; q++) acc[j][nf][q] = 0.f;

        #pragma unroll
        for (int ky = 0; ky < 3; ky++) {
            const uint32_t* ap = ab + ky * P32;
            uint32_t a00 = ap[0], a01 = ap[2 * P32],     a02 = ap[4],  a03 = ap[2 * P32 + 4];
            uint32_t a10 = ap[8], a11 = ap[2 * P32 + 8], a12 = ap[12], a13 = ap[2 * P32 + 12];
            const uint32_t* bp = B32 + ky * 8 * SB + t * SB + g;
            #pragma unroll
            for (int nf = 0; nf < NF; nf++) {
                uint32_t b0 = bp[nf * 8], b1 = bp[4 * SB + nf * 8];
                mma16(acc[0][nf], a00, a01, a02, a03, b0, b1);
                mma16(acc[1][nf], a10, a11, a12, a13, b0, b1);
            }
        }
        epi<0, OCR, 32, LEAKY>(acc[0], NF, ty, tx0,     g, t, b_s, outp);
        epi<0, OCR, 32, LEAKY>(acc[1], NF, ty, tx0 + 1, g, t, b_s, outp);
    }
}

// Fused: blocks [0,1024) shared conv1; [1024,2048) private conv.
__global__ __launch_bounds__(256) void conv_first_fused(
        const float* __restrict__ x_s, const float* __restrict__ Wsw,
        const float* __restrict__ Wsb,
        const float* __restrict__ x_p, const float* __restrict__ Pcw,
        const float* __restrict__ Pcb, const int* __restrict__ dom,
        uint32_t* __restrict__ s1, uint32_t* __restrict__ p1) {
    if (blockIdx.x < 1024)
        conv_first_body<36, 40, false, false>(blockIdx.x, x_s, Wsw, Wsb, nullptr, s1);
    else
        conv_first_body<12, 16, true, true>(blockIdx.x - 1024, x_p, Pcw, Pcb, dom, p1);
}

// ---------------------------------------------------------------------------
// Mid conv: 36->36, NHWC bf16 in, conv+bias+relu+pool. ldmatrix.x4 A path.
// Pixel stride 20 u32 (80B, 16B-aligned); row pitch 688/368 u32 (byte pitch
// ==64 mod 128 -> ldmatrix conflict-free). K per ky: 8 k16 frags over 64 u32
// (ch-gap & 4th-pixel slots carry zero weights).
// ---------------------------------------------------------------------------
template <int HH, int MODE>
__global__ __launch_bounds__(256) void conv_mid_k(const __nv_bfloat16* __restrict__ in,
                                                  const float* __restrict__ W,
                                                  const float* __restrict__ bias,
                                                  void* __restrict__ outv) {
    constexpr int P32  = (HH == 32) ? 688 : 368;
    constexpr int ROWS = HH + 2;
    constexpr int TX   = HH / 4;
    constexpr int NST  = HH * HH / 32;
    constexpr int PO   = HH / 2;
    extern __shared__ uint32_t sm32[];
    uint32_t* in32 = sm32;                         // ROWS*P32
    uint32_t* B32  = sm32 + ROWS * P32;            // 3*64*40 = 7680
    float*    b_s  = (float*)(B32 + 7680);

    int b = blockIdx.x, tid = threadIdx.x;
    // halo-only zero: rows 0/ROWS-1 full; rows 1..HH: cols [0,20) + [(HH+1)*20,P32)
    for (int i = tid; i < 2 * P32; i += 256)
        in32[(i < P32 ? 0 : ROWS - 1) * P32 + (i % P32)] = 0u;
    for (int i = tid; i < HH * 48; i += 256) {
        int rr = i / 48 + 1, cc = i % 48;
        in32[rr * P32 + (cc < 20 ? cc : (HH + 1) * 20 + (cc - 20))] = 0u;
    }
    const uint2* src2 = (const uint2*)(in + (size_t)b * HH * HH * 36);
    uint2* dst2 = (uint2*)in32;
    for (int i = tid; i < HH * HH * 10; i += 256) {   // q==9 writes the ch-gap zeros
        int p = i / 10, q = i - p * 10;
        int y = p / HH, xx = p % HH;
        uint2 v = (q < 9) ? src2[p * 9 + q] : make_uint2(0u, 0u);
        dst2[(((y + 1) * P32 + (xx + 1) * 20) >> 1) + q] = v;
    }
    for (int i = tid; i < 7680; i += 256) {
        int ky = i / 2560, rem = i - ky * 2560;
        int j = rem / 40, oc = rem % 40;
        int p = j / 20, jj = j - 20 * p;               // k u32 j -> pixel p, ch-pair jj
        float w0 = 0.f, w1 = 0.f;
        if (p < 3 && jj < 18 && oc < 36) {
            w0 = W[oc * 324 + (2 * jj) * 9 + ky * 3 + p];
            w1 = W[oc * 324 + (2 * jj + 1) * 9 + ky * 3 + p];
        }
        B32[i] = pkbf(w0, w1);
    }
    if (tid < 40) b_s[tid] = (tid < 36) ? bias[tid] : 0.f;
    __syncthreads();

    int lane = tid & 31, warp = tid >> 5;
    int g = lane >> 2, t = lane & 3;
    int r = lane & 15, kh = lane >> 4;
    int rowz = ((r & 7) >> 2) + 2 * (r >> 3);          // 0..3
    int colp = r & 3;
    uint32_t sbase = (uint32_t)__cvta_generic_to_shared(in32);
    void* outp;
    if (MODE == 0) outp = (void*)((uint32_t*)outv + (size_t)b * PO * PO * 18);
    else           outp = (void*)((float*)outv + (size_t)b * 36 * PO * PO);

    for (int s = warp; s < NST; s += 8) {
        int ty = (2 * s) / TX, tx0 = (2 * s) % TX;
        uint32_t abase = sbase + ((ty * 4 + rowz) * P32 + (tx0 * 4 + colp) * 20 + kh * 4) * 4;
        float acc[2][5][4];
        #pragma unroll
        for (int j = 0; j < 2; j++)
            #pragma unroll
            for (int nf = 0; nf < 5; nf++)
                #pragma unroll
                for (int q = 0; q < 4; q++) acc[j][nf][q] = 0.f;

        #pragma unroll
        for (int ky = 0; ky < 3; ky++) {
            uint32_t kbase = abase + ky * (P32 * 4);
            #pragma unroll
            for (int f = 0; f < 8; f++) {
                uint32_t A0[4], A1[4];
                ldsm4(A0, kbase + f * 32);
                ldsm4(A1, kbase + f * 32 + 320);       // +4 pixels
                const uint32_t* bp = B32 + ky * 2560 + (f * 8 + t) * 40 + g;
                #pragma unroll
                for (int nf = 0; nf < 5; nf++) {
                    uint32_t b0 = bp[nf * 8], b1 = bp[160 + nf * 8];
                    mma16(acc[0][nf], A0[0], A0[1], A0[2], A0[3], b0, b1);
                    mma16(acc[1][nf], A1[0], A1[1], A1[2], A1[3], b0, b1);
                }
            }
        }
        epi<MODE, 36, PO, false>(acc[0], 5, ty, tx0,     g, t, b_s, outp);
        epi<MODE, 36, PO, false>(acc[1], 5, ty, tx0 + 1, g, t, b_s, outp);
    }
}

// ---------------------------------------------------------------------------
// One-time permute of Pl_W[dom] to NHWC-K order (coalesced writes).
// ---------------------------------------------------------------------------
__global__ void permute_pw_k(const float* __restrict__ Pl_W,
                             const int* __restrict__ dom,
                             float* __restrict__ pw) {
    int d = *dom;
    const float* W = Pl_W + (size_t)d * 147456;
    for (int i = blockIdx.x * 256 + threadIdx.x; i < 147456; i += gridDim.x * 256) {
        int o = i / 12288, rr = i - o * 12288;
        int p = rr / 12, c = rr - 12 * p;
        pw[i] = W[o * 12288 + c * 1024 + p];
    }
}

// ---------------------------------------------------------------------------
// Fused FCs: warp-per-sample, 8 samples/block.
// blocks [0,128): shared fc (f32 in, K=2304, relu) -> g_h
// blocks [128,256): private fc (bf16 NHWC in, K=12288 via g_pw) -> g_pf
// ---------------------------------------------------------------------------
__device__ void fc_shared_body(int b, const float* __restrict__ in,
                               const float* __restrict__ W,
                               const float* __restrict__ bias,
                               float* __restrict__ out) {
    extern __shared__ float ws[];
    int tid = threadIdx.x, lane = tid & 31, warp = tid >> 5;
    for (int i = tid; i < 12 * 2304; i += 256) ws[i] = W[i];
    __syncthreads();
    int smp = b * 8 + warp;
    const float4* xp = (const float4*)(in + (size_t)smp * 2304);
    float acc[12];
    #pragma unroll
    for (int o = 0; o < 12; o++) acc[o] = 0.f;
    #pragma unroll 2
    for (int i = 0; i < 18; i++) {
        int k4 = lane + i * 32;
        float4 xa = xp[k4];
        #pragma unroll
        for (int o = 0; o < 12; o++) {
            float4 wa = ((const float4*)(ws + o * 2304))[k4];
            acc[o] = fmaf(xa.x, wa.x, fmaf(xa.y, wa.y,
                      fmaf(xa.z, wa.z, fmaf(xa.w, wa.w, acc[o]))));
        }
    }
    #pragma unroll
    for (int o = 0; o < 12; o++)
        #pragma unroll
        for (int off = 16; off; off >>= 1)
            acc[o] += __shfl_down_sync(0xffffffffu, acc[o], off);
    if (lane == 0)
        #pragma unroll
        for (int o = 0; o < 12; o++)
            out[smp * 12 + o] = fmaxf(acc[o] + bias[o], 0.f);
}

__device__ void fc_priv_body(int b, const __nv_bfloat16* __restrict__ in,
                             const float* __restrict__ pw,
                             const float* __restrict__ bias,
                             const int* __restrict__ dom,
                             float* __restrict__ out) {
    extern __shared__ float ws[];
    int d = *dom;
    int tid = threadIdx.x, lane = tid & 31, warp = tid >> 5;
    int smp = b * 8 + warp;
    const __nv_bfloat16* xp = in + (size_t)smp * 12288;
    float acc[12];
    #pragma unroll
    for (int o = 0; o < 12; o++) acc[o] = 0.f;

    for (int kc0 = 0; kc0 < 12288; kc0 += 2048) {
        __syncthreads();
        for (int i = tid; i < 12 * 2048; i += 256)
            ws[i] = pw[(size_t)(i >> 11) * 12288 + kc0 + (i & 2047)];
        __syncthreads();
        const uint2* x2 = (const uint2*)(xp + kc0);
        #pragma unroll 2
        for (int i = 0; i < 16; i++) {
            int k4 = lane + i * 32;
            uint2 xa = x2[k4];
            float2 x01 = __bfloat1622float2(*(const __nv_bfloat162*)&xa.x);
            float2 x23 = __bfloat1622float2(*(const __nv_bfloat162*)&xa.y);
            #pragma unroll
            for (int o = 0; o < 12; o++) {
                float4 wa = ((const float4*)(ws + o * 2048))[k4];
                acc[o] = fmaf(x01.x, wa.x, fmaf(x01.y, wa.y,
                          fmaf(x23.x, wa.z, fmaf(x23.y, wa.w, acc[o]))));
            }
        }
    }
    #pragma unroll
    for (int o = 0; o < 12; o++)
        #pragma unroll
        for (int off = 16; off; off >>= 1)
            acc[o] += __shfl_down_sync(0xffffffffu, acc[o], off);
    if (lane == 0)
        #pragma unroll
        for (int o = 0; o < 12; o++)
            out[smp * 12 + o] = acc[o] + bias[d * 12 + o];
}

__global__ __launch_bounds__(256) void fc_fused(
        const float* __restrict__ s3, const float* __restrict__ Wfc,
        const float* __restrict__ bfc, float* __restrict__ hb,
        const __nv_bfloat16* __restrict__ p1, const float* __restrict__ pw,
        const float* __restrict__ Plb, const int* __restrict__ dom,
        float* __restrict__ pf) {
    if (blockIdx.x < 128) fc_shared_body(blockIdx.x, s3, Wfc, bfc, hb);
    else                  fc_priv_body(blockIdx.x - 128, p1, pw, Plb, dom, pf);
}

// ---------------------------------------------------------------------------
// Per-sample task-routed heads.
// ---------------------------------------------------------------------------
__global__ void heads_k(const float* __restrict__ h, const float* __restrict__ p,
                        const int* __restrict__ tt,
                        const float* __restrict__ W1, const float* __restrict__ b1,
                        const float* __restrict__ W2, const float* __restrict__ b2,
                        const float* __restrict__ W3, const float* __restrict__ b3,
                        float* __restrict__ out) {
    int bi = blockIdx.x * blockDim.x + threadIdx.x;
    if (bi >= 1024) return;
    int t = tt[bi];
    float x[24];
    #pragma unroll
    for (int i = 0; i < 12; i++) { x[i] = h[bi * 12 + i]; x[12 + i] = p[bi * 12 + i]; }
    float h1[28];
    const float* w1 = W1 + t * 28 * 24;
    #pragma unroll
    for (int i = 0; i < 28; i++) {
        float s = b1[t * 28 + i];
        #pragma unroll
        for (int j = 0; j < 24; j++) s = fmaf(w1[i * 24 + j], x[j], s);
        h1[i] = fmaxf(s, 0.f);
    }
    float h2[14];
    const float* w2 = W2 + t * 14 * 28;
    #pragma unroll
    for (int i = 0; i < 14; i++) {
        float s = b2[t * 14 + i];
        #pragma unroll
        for (int j = 0; j < 28; j++) s = fmaf(w2[i * 28 + j], h1[j], s);
        h2[i] = fmaxf(s, 0.f);
    }
    const float* w3 = W3 + t * 5 * 14;
    #pragma unroll
    for (int i = 0; i < 5; i++) {
        float s = b3[t * 5 + i];
        #pragma unroll
        for (int j = 0; j < 14; j++) s = fmaf(w3[i * 14 + j], h2[j], s);
        out[bi * 5 + i] = s;
    }
}

// ---------------------------------------------------------------------------
// Launch
// ---------------------------------------------------------------------------
extern "C" void kernel_launch(void* const* d_in, const int* in_sizes, int n_in,
                              void* d_out, int out_size) {
    const float* x_s      = (const float*)d_in[0];
    const float* x_p      = (const float*)d_in[1];
    const int*   tt       = (const int*)  d_in[2];
    const int*   dom      = (const int*)  d_in[3];
    const float* Ws_in_W  = (const float*)d_in[4];
    const float* Ws_in_b  = (const float*)d_in[5];
    const float* Ws_hid_W = (const float*)d_in[6];
    const float* Ws_hid_b = (const float*)d_in[7];
    const float* Ws_fc_W  = (const float*)d_in[8];
    const float* Ws_fc_b  = (const float*)d_in[9];
    const float* Pc_W     = (const float*)d_in[10];
    const float* Pc_b     = (const float*)d_in[11];
    const float* Pl_W     = (const float*)d_in[12];
    const float* Pl_b     = (const float*)d_in[13];
    const float* H1W      = (const float*)d_in[14];
    const float* H1b      = (const float*)d_in[15];
    const float* H2W      = (const float*)d_in[16];
    const float* H2b      = (const float*)d_in[17];
    const float* H3W      = (const float*)d_in[18];
    const float* H3b      = (const float*)d_in[19];
    float* out = (float*)d_out;

    __nv_bfloat16 *s1, *s2, *p1;
    float *s3, *hb, *pf, *pw;
    cudaGetSymbolAddress((void**)&s1, g_s1);
    cudaGetSymbolAddress((void**)&s2, g_s2);
    cudaGetSymbolAddress((void**)&s3, g_s3);
    cudaGetSymbolAddress((void**)&hb, g_h);
    cudaGetSymbolAddress((void**)&p1, g_p1);
    cudaGetSymbolAddress((void**)&pf, g_pf);
    cudaGetSymbolAddress((void**)&pw, g_pw);

    const int SM_CF  = (66 * 144 + 3 * 8 * 40 + 40) * 4;     // 42016
    const int SM_M32 = (34 * 688 + 7680 + 40) * 4;           // 124448
    const int SM_M16 = (18 * 368 + 7680 + 40) * 4;           // 57376
    const int SM_FC  = 12 * 2304 * 4;                        // 110592

    cudaFuncSetAttribute((const void*)conv_first_fused,
                         cudaFuncAttributeMaxDynamicSharedMemorySize, SM_CF);
    cudaFuncSetAttribute((const void*)conv_mid_k<32, 0>,
                         cudaFuncAttributeMaxDynamicSharedMemorySize, SM_M32);
    cudaFuncSetAttribute((const void*)conv_mid_k<16, 1>,
                         cudaFuncAttributeMaxDynamicSharedMemorySize, SM_M16);
    cudaFuncSetAttribute((const void*)fc_fused,
                         cudaFuncAttributeMaxDynamicSharedMemorySize, SM_FC);

    permute_pw_k<<<64, 256>>>(Pl_W, dom, pw);
    conv_first_fused<<<2048, 256, SM_CF>>>(x_s, Ws_in_W, Ws_in_b,
                                           x_p, Pc_W, Pc_b, dom,
                                           (uint32_t*)s1, (uint32_t*)p1);
    conv_mid_k<32, 0><<<1024, 256, SM_M32>>>(s1, Ws_hid_W, Ws_hid_b, (void*)s2);
    conv_mid_k<16, 1><<<1024, 256, SM_M16>>>(s2, Ws_hid_W, Ws_hid_b, (void*)s3);
    fc_fused<<<256, 256, SM_FC>>>(s3, Ws_fc_W, Ws_fc_b, hb, p1, pw, Pl_b, dom, pf);
    heads_k<<<4, 256>>>(hb, pf, tt, H1W, H1b, H2W, H2b, H3W, H3b, out);
}

// round 12
// speedup vs baseline: 1.9090x; 1.1144x over previous
#include <cuda_runtime.h>
#include <cuda_bf16.h>
#include <cstdint>

// ---------------------------------------------------------------------------
// helpers
// ---------------------------------------------------------------------------
__device__ __forceinline__ uint32_t pkbf(float lo, float hi) {
    uint32_t r; asm("cvt.rn.bf16x2.f32 %0,%1,%2;" : "=r"(r) : "f"(hi), "f"(lo));
    return r;
}
__device__ __forceinline__ void mma16(float* c, uint32_t a0, uint32_t a1,
                                      uint32_t a2, uint32_t a3,
                                      uint32_t b0, uint32_t b1) {
    asm("mma.sync.aligned.m16n8k16.row.col.f32.bf16.bf16.f32 "
        "{%0,%1,%2,%3},{%4,%5,%6,%7},{%8,%9},{%0,%1,%2,%3};"
        : "+f"(c[0]), "+f"(c[1]), "+f"(c[2]), "+f"(c[3])
        : "r"(a0), "r"(a1), "r"(a2), "r"(a3), "r"(b0), "r"(b1));
}
__device__ __forceinline__ void ldsm4(uint32_t* a, uint32_t saddr) {
    asm volatile("ldmatrix.sync.aligned.m8n8.x4.shared.b16 {%0,%1,%2,%3},[%4];"
                 : "=r"(a[0]), "=r"(a[1]), "=r"(a[2]), "=r"(a[3]) : "r"(saddr));
}

// ---------------------------------------------------------------------------
// Scratch
// ---------------------------------------------------------------------------
__device__ __nv_bfloat16 g_s1[1024 * 32 * 32 * 36];  // conv1 out, NHWC bf16
__device__ __nv_bfloat16 g_s2[1024 * 16 * 16 * 36];  // conv2 out, NHWC bf16
__device__ float         g_s3[1024 * 36 * 8 * 8];    // conv3 out, NCHW f32
__device__ float         g_h [1024 * 12];
__device__ __nv_bfloat16 g_p1[1024 * 32 * 32 * 12];  // private conv, NHWC bf16
__device__ float         g_pf[1024 * 12];
__device__ float         g_pw[12 * 12288];           // Pl_W[dom] permuted (NHWC K)
__device__ uint32_t      g_bf1[960];                 // packed first-conv B (shared)
__device__ uint32_t      g_bfp[960];                 // packed first-conv B (private)
__device__ uint32_t      g_bmid[7680];               // packed mid-conv B

// ---------------------------------------------------------------------------
// One-time prep: pack all conv weights into ready-to-copy SMEM images + pw.
// ---------------------------------------------------------------------------
__global__ void prep_k(const float* __restrict__ Ws_in_W,
                       const float* __restrict__ Pc_W,
                       const int*   __restrict__ dom,
                       const float* __restrict__ Ws_hid_W,
                       const float* __restrict__ Pl_W,
                       float* __restrict__ pw,
                       uint32_t* __restrict__ bf1,
                       uint32_t* __restrict__ bfp,
                       uint32_t* __restrict__ bmid) {
    int d = *dom;
    const float* Wp = Pc_W + d * 12 * 27;
    const float* Wl = Pl_W + (size_t)d * 147456;
    const int TOT = 960 + 960 + 7680 + 147456;
    for (int i = blockIdx.x * 256 + threadIdx.x; i < TOT; i += gridDim.x * 256) {
        if (i < 960) {                                  // first conv, shared (36 oc)
            int ky = i / 320, rem = i % 320, j = rem / 40, oc = rem % 40;
            int kx = j >> 1, ch0 = (j & 1) * 2;
            float w0 = 0.f, w1 = 0.f;
            if (oc < 36 && kx < 3) {
                w0 = Ws_in_W[oc * 27 + ch0 * 9 + ky * 3 + kx];
                if (ch0 + 1 < 3) w1 = Ws_in_W[oc * 27 + (ch0 + 1) * 9 + ky * 3 + kx];
            }
            bf1[i] = pkbf(w0, w1);
        } else if (i < 1920) {                          // first conv, private (12 oc)
            int ii = i - 960;
            int ky = ii / 320, rem = ii % 320, j = rem / 40, oc = rem % 40;
            int kx = j >> 1, ch0 = (j & 1) * 2;
            float w0 = 0.f, w1 = 0.f;
            if (oc < 12 && kx < 3) {
                w0 = Wp[oc * 27 + ch0 * 9 + ky * 3 + kx];
                if (ch0 + 1 < 3) w1 = Wp[oc * 27 + (ch0 + 1) * 9 + ky * 3 + kx];
            }
            bfp[ii] = pkbf(w0, w1);
        } else if (i < 9600) {                          // mid conv B image
            int ii = i - 1920;
            int ky = ii / 2560, rem = ii - ky * 2560;
            int j = rem / 40, oc = rem % 40;
            int p = j / 20, jj = j - 20 * p;
            float w0 = 0.f, w1 = 0.f;
            if (p < 3 && jj < 18 && oc < 36) {
                w0 = Ws_hid_W[oc * 324 + (2 * jj) * 9 + ky * 3 + p];
                w1 = Ws_hid_W[oc * 324 + (2 * jj + 1) * 9 + ky * 3 + p];
            }
            bmid[ii] = pkbf(w0, w1);
        } else {                                        // Pl_W permute to NHWC-K
            int ii = i - 9600;
            int o = ii / 12288, rr = ii - o * 12288;
            int p = rr / 12, c = rr - 12 * p;
            pw[ii] = Wl[o * 12288 + c * 1024 + p];
        }
    }
}

// ---------------------------------------------------------------------------
// Epilogue: in-fragment 2x2 maxpool via shfl, bias+act, store.
// MODE 0: NHWC bf16 (u32 pairs); MODE 1: NCHW f32.
// ---------------------------------------------------------------------------
template <int MODE, int OCR, int PO, bool LEAKY>
__device__ __forceinline__ void epi(const float acc[][4], int NF,
                                    int ty, int tx, int g, int t,
                                    const float* b_s, void* outp) {
    for (int nf = 0; nf < NF; nf++) {
        float v0 = acc[nf][0], v1 = acc[nf][1], v2 = acc[nf][2], v3 = acc[nf][3];
        v0 = fmaxf(v0, __shfl_xor_sync(0xffffffffu, v0, 4));
        v1 = fmaxf(v1, __shfl_xor_sync(0xffffffffu, v1, 4));
        v2 = fmaxf(v2, __shfl_xor_sync(0xffffffffu, v2, 4));
        v3 = fmaxf(v3, __shfl_xor_sync(0xffffffffu, v3, 4));
        v0 = fmaxf(v0, __shfl_xor_sync(0xffffffffu, v0, 16));
        v1 = fmaxf(v1, __shfl_xor_sync(0xffffffffu, v1, 16));
        v2 = fmaxf(v2, __shfl_xor_sync(0xffffffffu, v2, 16));
        v3 = fmaxf(v3, __shfl_xor_sync(0xffffffffu, v3, 16));
        int oc = nf * 8 + 2 * t;
        if (((g & 1) == 0) && (g < 4) && oc < OCR) {
            int px  = tx * 2 + (g >> 1);
            int py0 = ty * 2;
            float b0 = b_s[oc], b1 = b_s[oc + 1];
            float o00 = v0 + b0, o01 = v1 + b1, o10 = v2 + b0, o11 = v3 + b1;
            if (LEAKY) {
                o00 = o00 > 0.f ? o00 : 0.001f * o00;
                o01 = o01 > 0.f ? o01 : 0.001f * o01;
                o10 = o10 > 0.f ? o10 : 0.001f * o10;
                o11 = o11 > 0.f ? o11 : 0.001f * o11;
            } else {
                o00 = fmaxf(o00, 0.f); o01 = fmaxf(o01, 0.f);
                o10 = fmaxf(o10, 0.f); o11 = fmaxf(o11, 0.f);
            }
            if (MODE == 0) {
                uint32_t* o32 = (uint32_t*)outp;
                constexpr int ST = OCR / 2;
                o32[( py0      * PO + px) * ST + (oc >> 1)] = pkbf(o00, o01);
                o32[((py0 + 1) * PO + px) * ST + (oc >> 1)] = pkbf(o10, o11);
            } else {
                float* of = (float*)outp;
                of[( oc      * PO + py0)     * PO + px] = o00;
                of[((oc + 1) * PO + py0)     * PO + px] = o01;
                of[( oc      * PO + py0 + 1) * PO + px] = o10;
                of[((oc + 1) * PO + py0 + 1) * PO + px] = o11;
            }
        }
    }
}

// ---------------------------------------------------------------------------
// First-conv body: Cin=3 (4ch-padded NHWC bf16), H=64, conv+bias+act+pool.
// Weights staged as uint4 copies from prepped image.
// ---------------------------------------------------------------------------
template <int OCR, int OCP, bool LEAKY, bool USE_DOM>
__device__ void conv_first_body(int b, const float* __restrict__ x,
                                const uint32_t* __restrict__ pb,
                                const float* __restrict__ bias,
                                const int* __restrict__ dom,
                                uint32_t* __restrict__ outb) {
    constexpr int P32 = 144;
    constexpr int NF  = OCP / 8;
    constexpr int SB  = 40;
    extern __shared__ uint32_t sm32[];
    uint32_t* in32 = sm32;                     // 66*144
    uint32_t* B32  = sm32 + 66 * P32;          // 960
    float*    b_s  = (float*)(B32 + 960);

    int tid = threadIdx.x;
    if (USE_DOM) { int d = *dom; bias += d * OCR; }

    // weights: plain uint4 copy
    {
        uint4* B4 = (uint4*)B32;
        const uint4* pb4 = (const uint4*)pb;
        for (int i = tid; i < 240; i += 256) B4[i] = pb4[i];
    }
    // halo-only zero: rows 0/65 full; rows 1..64 cols {0,1} U [130,144)
    for (int i = tid; i < 2 * P32; i += 256)
        in32[(i < P32 ? 0 : 65) * P32 + (i % P32)] = 0u;
    for (int i = tid; i < 64 * 16; i += 256) {
        int rr = i / 16 + 1, cc = i % 16;
        in32[rr * P32 + (cc < 2 ? cc : 128 + cc)] = 0u;
    }
    const float* src = x + (size_t)b * 3 * 4096;
    for (int p = tid; p < 4096; p += 256) {
        int y = p >> 6, xx = p & 63;
        int dst = (y + 1) * P32 + (xx + 1) * 2;
        in32[dst]     = pkbf(src[p], src[4096 + p]);
        in32[dst + 1] = pkbf(src[8192 + p], 0.f);
    }
    if (tid < OCP) b_s[tid] = (tid < OCR) ? bias[tid] : 0.f;
    __syncthreads();

    int lane = tid & 31, warp = tid >> 5;
    int g = lane >> 2, t = lane & 3;
    int dy = g >> 2, dxl = g & 3;
    uint32_t* outp = outb + (size_t)b * 32 * 32 * (OCR / 2);

    for (int s = warp; s < 128; s += 8) {
        int ty = s >> 3, tx0 = (2 * s) & 15;
        const uint32_t* ab = in32 + (ty * 4 + dy) * P32 + (tx0 * 4 + dxl) * 2 + t;
        float acc[2][NF][4];
        #pragma unroll
        for (int j = 0; j < 2; j++)
            #pragma unroll
            for (int nf = 0; nf < NF; nf++)
                #pragma unroll
                for (int q = 0; q < 4; q++) acc[j][nf][q] = 0.f;

        #pragma unroll
        for (int ky = 0; ky < 3; ky++) {
            const uint32_t* ap = ab + ky * P32;
            uint32_t a00 = ap[0], a01 = ap[2 * P32],     a02 = ap[4],  a03 = ap[2 * P32 + 4];
            uint32_t a10 = ap[8], a11 = ap[2 * P32 + 8], a12 = ap[12], a13 = ap[2 * P32 + 12];
            const uint32_t* bp = B32 + ky * 8 * SB + t * SB + g;
            #pragma unroll
            for (int nf = 0; nf < NF; nf++) {
                uint32_t b0 = bp[nf * 8], b1 = bp[4 * SB + nf * 8];
                mma16(acc[0][nf], a00, a01, a02, a03, b0, b1);
                mma16(acc[1][nf], a10, a11, a12, a13, b0, b1);
            }
        }
        epi<0, OCR, 32, LEAKY>(acc[0], NF, ty, tx0,     g, t, b_s, outp);
        epi<0, OCR, 32, LEAKY>(acc[1], NF, ty, tx0 + 1, g, t, b_s, outp);
    }
}

// Fused: blocks [0,1024) shared conv1; [1024,2048) private conv.
__global__ __launch_bounds__(256) void conv_first_fused(
        const float* __restrict__ x_s, const uint32_t* __restrict__ bf1,
        const float* __restrict__ Wsb,
        const float* __restrict__ x_p, const uint32_t* __restrict__ bfp,
        const float* __restrict__ Pcb, const int* __restrict__ dom,
        uint32_t* __restrict__ s1, uint32_t* __restrict__ p1) {
    if (blockIdx.x < 1024)
        conv_first_body<36, 40, false, false>(blockIdx.x, x_s, bf1, Wsb, nullptr, s1);
    else
        conv_first_body<12, 16, true, true>(blockIdx.x - 1024, x_p, bfp, Pcb, dom, p1);
}

// ---------------------------------------------------------------------------
// Mid conv 32->16, split into 2 half-image CTAs (18-row window, 2 CTA/SM).
// blockIdx: b = idx>>1, h = idx&1 (top/bottom half). NHWC bf16 out.
// ---------------------------------------------------------------------------
__global__ __launch_bounds__(256) void conv_mid32_k(const __nv_bfloat16* __restrict__ in,
                                                    const float* __restrict__ bias,
                                                    const uint32_t* __restrict__ bmid,
                                                    uint32_t* __restrict__ outb) {
    constexpr int P32 = 688, RL = 18;
    extern __shared__ uint32_t sm32[];
    uint32_t* in32 = sm32;                     // 18*688
    uint32_t* B32  = sm32 + RL * P32;          // 7680
    float*    b_s  = (float*)(B32 + 7680);

    int b = blockIdx.x >> 1, h = blockIdx.x & 1, tid = threadIdx.x;

    {
        uint4* B4 = (uint4*)B32;
        const uint4* pb4 = (const uint4*)bmid;
        for (int i = tid; i < 1920; i += 256) B4[i] = pb4[i];
    }
    // out-of-range row fully zero; L/R halos zero on all rows
    int lr_bad = h ? 17 : 0;
    for (int i = tid; i < P32; i += 256) in32[lr_bad * P32 + i] = 0u;
    for (int i = tid; i < RL * 48; i += 256) {
        int lr = i / 48, cc = i % 48;
        in32[lr * P32 + (cc < 20 ? cc : 660 + (cc - 20))] = 0u;
    }
    const uint2* src2 = (const uint2*)(in + (size_t)b * 32 * 32 * 36);
    uint2* dst2 = (uint2*)in32;
    for (int i = tid; i < 17 * 32 * 10; i += 256) {
        int lrv = i / 320, rem = i - lrv * 320;
        int xx = rem / 10, q = rem - xx * 10;
        int lr = lrv + (h ? 0 : 1);
        int gy = h * 16 - 1 + lr;
        uint2 v = (q < 9) ? src2[(gy * 32 + xx) * 9 + q] : make_uint2(0u, 0u);
        dst2[((lr * P32 + (xx + 1) * 20) >> 1) + q] = v;
    }
    if (tid < 40) b_s[tid] = (tid < 36) ? bias[tid] : 0.f;
    __syncthreads();

    int lane = tid & 31, warp = tid >> 5;
    int g = lane >> 2, t = lane & 3;
    int r = lane & 15, kh = lane >> 4;
    int rowz = ((r & 7) >> 2) + 2 * (r >> 3);
    int colp = r & 3;
    uint32_t sbase = (uint32_t)__cvta_generic_to_shared(in32);
    uint32_t* outp = outb + (size_t)b * 16 * 16 * 18;

    for (int s = warp; s < 16; s += 8) {
        int ty_l = (2 * s) / 8, tx0 = (2 * s) % 8;
        uint32_t abase = sbase + ((ty_l * 4 + rowz) * P32 + (tx0 * 4 + colp) * 20 + kh * 4) * 4;
        float acc[2][5][4];
        #pragma unroll
        for (int j = 0; j < 2; j++)
            #pragma unroll
            for (int nf = 0; nf < 5; nf++)
                #pragma unroll
                for (int q = 0; q < 4; q++) acc[j][nf][q] = 0.f;

        #pragma unroll
        for (int ky = 0; ky < 3; ky++) {
            uint32_t kbase = abase + ky * (P32 * 4);
            #pragma unroll
            for (int f = 0; f < 8; f++) {
                uint32_t A0[4], A1[4];
                ldsm4(A0, kbase + f * 32);
                ldsm4(A1, kbase + f * 32 + 320);
                const uint32_t* bp = B32 + ky * 2560 + (f * 8 + t) * 40 + g;
                #pragma unroll
                for (int nf = 0; nf < 5; nf++) {
                    uint32_t b0 = bp[nf * 8], b1 = bp[160 + nf * 8];
                    mma16(acc[0][nf], A0[0], A0[1], A0[2], A0[3], b0, b1);
                    mma16(acc[1][nf], A1[0], A1[1], A1[2], A1[3], b0, b1);
                }
            }
        }
        epi<0, 36, 16, false>(acc[0], 5, ty_l + h * 4, tx0,     g, t, b_s, outp);
        epi<0, 36, 16, false>(acc[1], 5, ty_l + h * 4, tx0 + 1, g, t, b_s, outp);
    }
}

// ---------------------------------------------------------------------------
// Mid conv 16->8: one block per image, NCHW f32 out.
// ---------------------------------------------------------------------------
__global__ __launch_bounds__(256) void conv_mid16_k(const __nv_bfloat16* __restrict__ in,
                                                    const float* __restrict__ bias,
                                                    const uint32_t* __restrict__ bmid,
                                                    float* __restrict__ outf) {
    constexpr int P32 = 368, ROWS = 18, HH = 16;
    extern __shared__ uint32_t sm32[];
    uint32_t* in32 = sm32;                     // 18*368
    uint32_t* B32  = sm32 + ROWS * P32;        // 7680
    float*    b_s  = (float*)(B32 + 7680);

    int b = blockIdx.x, tid = threadIdx.x;
    {
        uint4* B4 = (uint4*)B32;
        const uint4* pb4 = (const uint4*)bmid;
        for (int i = tid; i < 1920; i += 256) B4[i] = pb4[i];
    }
    for (int i = tid; i < 2 * P32; i += 256)
        in32[(i < P32 ? 0 : ROWS - 1) * P32 + (i % P32)] = 0u;
    for (int i = tid; i < HH * 48; i += 256) {
        int rr = i / 48 + 1, cc = i % 48;
        in32[rr * P32 + (cc < 20 ? cc : (HH + 1) * 20 + (cc - 20))] = 0u;
    }
    const uint2* src2 = (const uint2*)(in + (size_t)b * HH * HH * 36);
    uint2* dst2 = (uint2*)in32;
    for (int i = tid; i < HH * HH * 10; i += 256) {
        int p = i / 10, q = i - p * 10;
        int y = p / HH, xx = p % HH;
        uint2 v = (q < 9) ? src2[p * 9 + q] : make_uint2(0u, 0u);
        dst2[(((y + 1) * P32 + (xx + 1) * 20) >> 1) + q] = v;
    }
    if (tid < 40) b_s[tid] = (tid < 36) ? bias[tid] : 0.f;
    __syncthreads();

    int lane = tid & 31, warp = tid >> 5;
    int g = lane >> 2, t = lane & 3;
    int r = lane & 15, kh = lane >> 4;
    int rowz = ((r & 7) >> 2) + 2 * (r >> 3);
    int colp = r & 3;
    uint32_t sbase = (uint32_t)__cvta_generic_to_shared(in32);
    float* outp = outf + (size_t)b * 36 * 8 * 8;

    for (int s = warp; s < 8; s += 8) {
        int ty = (2 * s) / 4, tx0 = (2 * s) % 4;
        uint32_t abase = sbase + ((ty * 4 + rowz) * P32 + (tx0 * 4 + colp) * 20 + kh * 4) * 4;
        float acc[2][5][4];
        #pragma unroll
        for (int j = 0; j < 2; j++)
            #pragma unroll
            for (int nf = 0; nf < 5; nf++)
                #pragma unroll
                for (int q = 0; q < 4; q++) acc[j][nf][q] = 0.f;

        #pragma unroll
        for (int ky = 0; ky < 3; ky++) {
            uint32_t kbase = abase + ky * (P32 * 4);
            #pragma unroll
            for (int f = 0; f < 8; f++) {
                uint32_t A0[4], A1[4];
                ldsm4(A0, kbase + f * 32);
                ldsm4(A1, kbase + f * 32 + 320);
                const uint32_t* bp = B32 + ky * 2560 + (f * 8 + t) * 40 + g;
                #pragma unroll
                for (int nf = 0; nf < 5; nf++) {
                    uint32_t b0 = bp[nf * 8], b1 = bp[160 + nf * 8];
                    mma16(acc[0][nf], A0[0], A0[1], A0[2], A0[3], b0, b1);
                    mma16(acc[1][nf], A1[0], A1[1], A1[2], A1[3], b0, b1);
                }
            }
        }
        epi<1, 36, 8, false>(acc[0], 5, ty, tx0,     g, t, b_s, outp);
        epi<1, 36, 8, false>(acc[1], 5, ty, tx0 + 1, g, t, b_s, outp);
    }
}

// ---------------------------------------------------------------------------
// Fused FCs: warp-per-sample, 8 samples/block.
// blocks [0,128): shared fc (f32 in, K=2304, relu) -> g_h
// blocks [128,256): private fc (bf16 NHWC in, K=12288 via g_pw) -> g_pf
// ---------------------------------------------------------------------------
__device__ void fc_shared_body(int b, const float* __restrict__ in,
                               const float* __restrict__ W,
                               const float* __restrict__ bias,
                               float* __restrict__ out) {
    extern __shared__ float ws[];
    int tid = threadIdx.x, lane = tid & 31, warp = tid >> 5;
    for (int i = tid; i < 12 * 2304; i += 256) ws[i] = W[i];
    __syncthreads();
    int smp = b * 8 + warp;
    const float4* xp = (const float4*)(in + (size_t)smp * 2304);
    float acc[12];
    #pragma unroll
    for (int o = 0; o < 12; o++) acc[o] = 0.f;
    #pragma unroll 2
    for (int i = 0; i < 18; i++) {
        int k4 = lane + i * 32;
        float4 xa = xp[k4];
        #pragma unroll
        for (int o = 0; o < 12; o++) {
            float4 wa = ((const float4*)(ws + o * 2304))[k4];
            acc[o] = fmaf(xa.x, wa.x, fmaf(xa.y, wa.y,
                      fmaf(xa.z, wa.z, fmaf(xa.w, wa.w, acc[o]))));
        }
    }
    #pragma unroll
    for (int o = 0; o < 12; o++)
        #pragma unroll
        for (int off = 16; off; off >>= 1)
            acc[o] += __shfl_down_sync(0xffffffffu, acc[o], off);
    if (lane == 0)
        #pragma unroll
        for (int o = 0; o < 12; o++)
            out[smp * 12 + o] = fmaxf(acc[o] + bias[o], 0.f);
}

__device__ void fc_priv_body(int b, const __nv_bfloat16* __restrict__ in,
                             const float* __restrict__ pw,
                             const float* __restrict__ bias,
                             const int* __restrict__ dom,
                             float* __restrict__ out) {
    extern __shared__ float ws[];
    int d = *dom;
    int tid = threadIdx.x, lane = tid & 31, warp = tid >> 5;
    int smp = b * 8 + warp;
    const __nv_bfloat16* xp = in + (size_t)smp * 12288;
    float acc[12];
    #pragma unroll
    for (int o = 0; o < 12; o++) acc[o] = 0.f;

    for (int kc0 = 0; kc0 < 12288; kc0 += 2048) {
        __syncthreads();
        for (int i = tid; i < 12 * 2048; i += 256)
            ws[i] = pw[(size_t)(i >> 11) * 12288 + kc0 + (i & 2047)];
        __syncthreads();
        const uint2* x2 = (const uint2*)(xp + kc0);
        #pragma unroll 2
        for (int i = 0; i < 16; i++) {
            int k4 = lane + i * 32;
            uint2 xa = x2[k4];
            float2 x01 = __bfloat1622float2(*(const __nv_bfloat162*)&xa.x);
            float2 x23 = __bfloat1622float2(*(const __nv_bfloat162*)&xa.y);
            #pragma unroll
            for (int o = 0; o < 12; o++) {
                float4 wa = ((const float4*)(ws + o * 2048))[k4];
                acc[o] = fmaf(x01.x, wa.x, fmaf(x01.y, wa.y,
                          fmaf(x23.x, wa.z, fmaf(x23.y, wa.w, acc[o]))));
            }
        }
    }
    #pragma unroll
    for (int o = 0; o < 12; o++)
        #pragma unroll
        for (int off = 16; off; off >>= 1)
            acc[o] += __shfl_down_sync(0xffffffffu, acc[o], off);
    if (lane == 0)
        #pragma unroll
        for (int o = 0; o < 12; o++)
            out[smp * 12 + o] = acc[o] + bias[d * 12 + o];
}

__global__ __launch_bounds__(256) void fc_fused(
        const float* __restrict__ s3, const float* __restrict__ Wfc,
        const float* __restrict__ bfc, float* __restrict__ hb,
        const __nv_bfloat16* __restrict__ p1, const float* __restrict__ pw,
        const float* __restrict__ Plb, const int* __restrict__ dom,
        float* __restrict__ pf) {
    if (blockIdx.x < 128) fc_shared_body(blockIdx.x, s3, Wfc, bfc, hb);
    else                  fc_priv_body(blockIdx.x - 128, p1, pw, Plb, dom, pf);
}

// ---------------------------------------------------------------------------
// Per-sample task-routed heads.
// ---------------------------------------------------------------------------
__global__ void heads_k(const float* __restrict__ h, const float* __restrict__ p,
                        const int* __restrict__ tt,
                        const float* __restrict__ W1, const float* __restrict__ b1,
                        const float* __restrict__ W2, const float* __restrict__ b2,
                        const float* __restrict__ W3, const float* __restrict__ b3,
                        float* __restrict__ out) {
    int bi = blockIdx.x * blockDim.x + threadIdx.x;
    if (bi >= 1024) return;
    int t = tt[bi];
    float x[24];
    #pragma unroll
    for (int i = 0; i < 12; i++) { x[i] = h[bi * 12 + i]; x[12 + i] = p[bi * 12 + i]; }
    float h1[28];
    const float* w1 = W1 + t * 28 * 24;
    #pragma unroll
    for (int i = 0; i < 28; i++) {
        float s = b1[t * 28 + i];
        #pragma unroll
        for (int j = 0; j < 24; j++) s = fmaf(w1[i * 24 + j], x[j], s);
        h1[i] = fmaxf(s, 0.f);
    }
    float h2[14];
    const float* w2 = W2 + t * 14 * 28;
    #pragma unroll
    for (int i = 0; i < 14; i++) {
        float s = b2[t * 14 + i];
        #pragma unroll
        for (int j = 0; j < 28; j++) s = fmaf(w2[i * 28 + j], h1[j], s);
        h2[i] = fmaxf(s, 0.f);
    }
    const float* w3 = W3 + t * 5 * 14;
    #pragma unroll
    for (int i = 0; i < 5; i++) {
        float s = b3[t * 5 + i];
        #pragma unroll
        for (int j = 0; j < 14; j++) s = fmaf(w3[i * 14 + j], h2[j], s);
        out[bi * 5 + i] = s;
    }
}

// ---------------------------------------------------------------------------
// Launch
// ---------------------------------------------------------------------------
extern "C" void kernel_launch(void* const* d_in, const int* in_sizes, int n_in,
                              void* d_out, int out_size) {
    const float* x_s      = (const float*)d_in[0];
    const float* x_p      = (const float*)d_in[1];
    const int*   tt       = (const int*)  d_in[2];
    const int*   dom      = (const int*)  d_in[3];
    const float* Ws_in_W  = (const float*)d_in[4];
    const float* Ws_in_b  = (const float*)d_in[5];
    const float* Ws_hid_W = (const float*)d_in[6];
    const float* Ws_hid_b = (const float*)d_in[7];
    const float* Ws_fc_W  = (const float*)d_in[8];
    const float* Ws_fc_b  = (const float*)d_in[9];
    const float* Pc_W     = (const float*)d_in[10];
    const float* Pc_b     = (const float*)d_in[11];
    const float* Pl_W     = (const float*)d_in[12];
    const float* Pl_b     = (const float*)d_in[13];
    const float* H1W      = (const float*)d_in[14];
    const float* H1b      = (const float*)d_in[15];
    const float* H2W      = (const float*)d_in[16];
    const float* H2b      = (const float*)d_in[17];
    const float* H3W      = (const float*)d_in[18];
    const float* H3b      = (const float*)d_in[19];
    float* out = (float*)d_out;

    __nv_bfloat16 *s1, *s2, *p1;
    float *s3, *hb, *pf, *pw;
    uint32_t *bf1, *bfp, *bmid;
    cudaGetSymbolAddress((void**)&s1, g_s1);
    cudaGetSymbolAddress((void**)&s2, g_s2);
    cudaGetSymbolAddress((void**)&s3, g_s3);
    cudaGetSymbolAddress((void**)&hb, g_h);
    cudaGetSymbolAddress((void**)&p1, g_p1);
    cudaGetSymbolAddress((void**)&pf, g_pf);
    cudaGetSymbolAddress((void**)&pw, g_pw);
    cudaGetSymbolAddress((void**)&bf1, g_bf1);
    cudaGetSymbolAddress((void**)&bfp, g_bfp);
    cudaGetSymbolAddress((void**)&bmid, g_bmid);

    const int SM_CF  = (66 * 144 + 960 + 40) * 4;            // 42016
    const int SM_S32 = (18 * 688 + 7680 + 40) * 4;           // 80416
    const int SM_M16 = (18 * 368 + 7680 + 40) * 4;           // 57376
    const int SM_FC  = 12 * 2304 * 4;                        // 110592

    cudaFuncSetAttribute((const void*)conv_first_fused,
                         cudaFuncAttributeMaxDynamicSharedMemorySize, SM_CF);
    cudaFuncSetAttribute((const void*)conv_mid32_k,
                         cudaFuncAttributeMaxDynamicSharedMemorySize, SM_S32);
    cudaFuncSetAttribute((const void*)conv_mid16_k,
                         cudaFuncAttributeMaxDynamicSharedMemorySize, SM_M16);
    cudaFuncSetAttribute((const void*)fc_fused,
                         cudaFuncAttributeMaxDynamicSharedMemorySize, SM_FC);

    prep_k<<<64, 256>>>(Ws_in_W, Pc_W, dom, Ws_hid_W, Pl_W, pw, bf1, bfp, bmid);
    conv_first_fused<<<2048, 256, SM_CF>>>(x_s, bf1, Ws_in_b,
                                           x_p, bfp, Pc_b, dom,
                                           (uint32_t*)s1, (uint32_t*)p1);
    conv_mid32_k<<<2048, 256, SM_S32>>>(s1, Ws_hid_b, bmid, (uint32_t*)s2);
    conv_mid16_k<<<1024, 256, SM_M16>>>(s2, Ws_hid_b, bmid, s3);
    fc_fused<<<256, 256, SM_FC>>>(s3, Ws_fc_W, Ws_fc_b, hb, p1, pw, Pl_b, dom, pf);
    heads_k<<<4, 256>>>(hb, pf, tt, H1W, H1b, H2W, H2b, H3W, H3b, out);
}

// round 13
// speedup vs baseline: 1.9113x; 1.0012x over previous
#include <cuda_runtime.h>
#include <cuda_bf16.h>
#include <cstdint>

// ---------------------------------------------------------------------------
// helpers
// ---------------------------------------------------------------------------
__device__ __forceinline__ uint32_t pkbf(float lo, float hi) {
    uint32_t r; asm("cvt.rn.bf16x2.f32 %0,%1,%2;" : "=r"(r) : "f"(hi), "f"(lo));
    return r;
}
__device__ __forceinline__ void mma16(float* c, uint32_t a0, uint32_t a1,
                                      uint32_t a2, uint32_t a3,
                                      uint32_t b0, uint32_t b1) {
    asm("mma.sync.aligned.m16n8k16.row.col.f32.bf16.bf16.f32 "
        "{%0,%1,%2,%3},{%4,%5,%6,%7},{%8,%9},{%0,%1,%2,%3};"
        : "+f"(c[0]), "+f"(c[1]), "+f"(c[2]), "+f"(c[3])
        : "r"(a0), "r"(a1), "r"(a2), "r"(a3), "r"(b0), "r"(b1));
}
__device__ __forceinline__ void ldsm4(uint32_t* a, uint32_t saddr) {
    asm volatile("ldmatrix.sync.aligned.m8n8.x4.shared.b16 {%0,%1,%2,%3},[%4];"
                 : "=r"(a[0]), "=r"(a[1]), "=r"(a[2]), "=r"(a[3]) : "r"(saddr));
}
__device__ __forceinline__ uint32_t vmax2(uint32_t a, uint32_t b) {
    uint32_t r; asm("max.bf16x2 %0,%1,%2;" : "=r"(r) : "r"(a), "r"(b)); return r;
}
__device__ __forceinline__ uint32_t vmin2(uint32_t a, uint32_t b) {
    uint32_t r; asm("min.bf16x2 %0,%1,%2;" : "=r"(r) : "r"(a), "r"(b)); return r;
}
__device__ __forceinline__ uint32_t vfma2(uint32_t a, uint32_t b, uint32_t c) {
    uint32_t r; asm("fma.rn.bf16x2 %0,%1,%2,%3;" : "=r"(r) : "r"(a), "r"(b), "r"(c));
    return r;
}

// ---------------------------------------------------------------------------
// Scratch
// ---------------------------------------------------------------------------
__device__ __nv_bfloat16 g_s1[1024 * 32 * 32 * 36];  // conv1 out, NHWC bf16
__device__ __nv_bfloat16 g_s2[1024 * 16 * 16 * 36];  // conv2 out, NHWC bf16
__device__ __nv_bfloat16 g_s3[1024 * 8 * 8 * 36];    // conv3 out, NHWC bf16
__device__ float         g_h [1024 * 12];
__device__ __nv_bfloat16 g_p1[1024 * 32 * 32 * 12];  // private conv, NHWC bf16
__device__ float         g_pf[1024 * 12];
__device__ float         g_pw[12 * 12288];           // Pl_W[dom] permuted (NHWC K)
__device__ float         g_fw[12 * 2304];            // Ws_fc_W permuted (NHWC K)
__device__ uint32_t      g_bf1[960];                 // packed first-conv B (shared)
__device__ uint32_t      g_bfp[960];                 // packed first-conv B (private)
__device__ uint32_t      g_bmid[7680];               // packed mid-conv B

// ---------------------------------------------------------------------------
// One-time prep: pack conv weights into SMEM images; permute FC weights.
// ---------------------------------------------------------------------------
__global__ void prep_k(const float* __restrict__ Ws_in_W,
                       const float* __restrict__ Pc_W,
                       const int*   __restrict__ dom,
                       const float* __restrict__ Ws_hid_W,
                       const float* __restrict__ Pl_W,
                       const float* __restrict__ Ws_fc_W,
                       float* __restrict__ pw,
                       float* __restrict__ fw,
                       uint32_t* __restrict__ bf1,
                       uint32_t* __restrict__ bfp,
                       uint32_t* __restrict__ bmid) {
    int d = *dom;
    const float* Wp = Pc_W + d * 12 * 27;
    const float* Wl = Pl_W + (size_t)d * 147456;
    const int TOT = 960 + 960 + 7680 + 147456 + 27648;
    for (int i = blockIdx.x * 256 + threadIdx.x; i < TOT; i += gridDim.x * 256) {
        if (i < 960) {                                  // first conv, shared (36 oc)
            int ky = i / 320, rem = i % 320, j = rem / 40, oc = rem % 40;
            int kx = j >> 1, ch0 = (j & 1) * 2;
            float w0 = 0.f, w1 = 0.f;
            if (oc < 36 && kx < 3) {
                w0 = Ws_in_W[oc * 27 + ch0 * 9 + ky * 3 + kx];
                if (ch0 + 1 < 3) w1 = Ws_in_W[oc * 27 + (ch0 + 1) * 9 + ky * 3 + kx];
            }
            bf1[i] = pkbf(w0, w1);
        } else if (i < 1920) {                          // first conv, private (12 oc)
            int ii = i - 960;
            int ky = ii / 320, rem = ii % 320, j = rem / 40, oc = rem % 40;
            int kx = j >> 1, ch0 = (j & 1) * 2;
            float w0 = 0.f, w1 = 0.f;
            if (oc < 12 && kx < 3) {
                w0 = Wp[oc * 27 + ch0 * 9 + ky * 3 + kx];
                if (ch0 + 1 < 3) w1 = Wp[oc * 27 + (ch0 + 1) * 9 + ky * 3 + kx];
            }
            bfp[ii] = pkbf(w0, w1);
        } else if (i < 9600) {                          // mid conv B image
            int ii = i - 1920;
            int ky = ii / 2560, rem = ii - ky * 2560;
            int j = rem / 40, oc = rem % 40;
            int p = j / 20, jj = j - 20 * p;
            float w0 = 0.f, w1 = 0.f;
            if (p < 3 && jj < 18 && oc < 36) {
                w0 = Ws_hid_W[oc * 324 + (2 * jj) * 9 + ky * 3 + p];
                w1 = Ws_hid_W[oc * 324 + (2 * jj + 1) * 9 + ky * 3 + p];
            }
            bmid[ii] = pkbf(w0, w1);
        } else if (i < 9600 + 147456) {                 // Pl_W permute to NHWC-K
            int ii = i - 9600;
            int o = ii / 12288, rr = ii - o * 12288;
            int p = rr / 12, c = rr - 12 * p;
            pw[ii] = Wl[o * 12288 + c * 1024 + p];
        } else {                                        // Ws_fc_W permute to NHWC-K
            int ii = i - 9600 - 147456;
            int o = ii / 2304, rr = ii - o * 2304;
            int p = rr / 36, c = rr - 36 * p;
            fw[ii] = Ws_fc_W[o * 2304 + c * 64 + p];
        }
    }
}

// ---------------------------------------------------------------------------
// Packed epilogue: bias in f32, pack bf16x2, pool via 4 shfl + max.bf16x2,
// act in bf16x2, store NHWC u32 pairs. Identical numerics to f32-pool path
// (rounding is monotone).
// ---------------------------------------------------------------------------
template <int OCR, int PO, bool LEAKY>
__device__ __forceinline__ void epi_pk(const float acc[][4], int NF,
                                       int ty, int tx, int g, int t,
                                       const float* b_s, uint32_t* o32) {
    const uint32_t C001 = 0x3A833A83u;   // bf16x2(0.001, 0.001)
    for (int nf = 0; nf < NF; nf++) {
        int oc = nf * 8 + 2 * t;
        float b0 = b_s[oc], b1 = b_s[oc + 1];
        uint32_t p01 = pkbf(acc[nf][0] + b0, acc[nf][1] + b1);
        uint32_t p23 = pkbf(acc[nf][2] + b0, acc[nf][3] + b1);
        p01 = vmax2(p01, __shfl_xor_sync(0xffffffffu, p01, 4));
        p23 = vmax2(p23, __shfl_xor_sync(0xffffffffu, p23, 4));
        p01 = vmax2(p01, __shfl_xor_sync(0xffffffffu, p01, 16));
        p23 = vmax2(p23, __shfl_xor_sync(0xffffffffu, p23, 16));
        if (LEAKY) {
            p01 = vfma2(vmin2(p01, 0u), C001, vmax2(p01, 0u));
            p23 = vfma2(vmin2(p23, 0u), C001, vmax2(p23, 0u));
        } else {
            p01 = vmax2(p01, 0u);
            p23 = vmax2(p23, 0u);
        }
        if (((g & 1) == 0) && (g < 4) && oc < OCR) {
            int px  = tx * 2 + (g >> 1);
            int py0 = ty * 2;
            o32[( py0      * PO + px) * (OCR / 2) + (oc >> 1)] = p01;
            o32[((py0 + 1) * PO + px) * (OCR / 2) + (oc >> 1)] = p23;
        }
    }
}

// ---------------------------------------------------------------------------
// First-conv body: Cin=3 (4ch-padded NHWC bf16), H=64, conv+bias+act+pool.
// ---------------------------------------------------------------------------
template <int OCR, int OCP, bool LEAKY, bool USE_DOM>
__device__ void conv_first_body(int b, const float* __restrict__ x,
                                const uint32_t* __restrict__ pb,
                                const float* __restrict__ bias,
                                const int* __restrict__ dom,
                                uint32_t* __restrict__ outb) {
    constexpr int P32 = 144;
    constexpr int NF  = OCP / 8;
    constexpr int SB  = 40;
    extern __shared__ uint32_t sm32[];
    uint32_t* in32 = sm32;                     // 66*144
    uint32_t* B32  = sm32 + 66 * P32;          // 960
    float*    b_s  = (float*)(B32 + 960);

    int tid = threadIdx.x;
    if (USE_DOM) { int d = *dom; bias += d * OCR; }

    {
        uint4* B4 = (uint4*)B32;
        const uint4* pb4 = (const uint4*)pb;
        for (int i = tid; i < 240; i += 256) B4[i] = pb4[i];
    }
    for (int i = tid; i < 2 * P32; i += 256)
        in32[(i < P32 ? 0 : 65) * P32 + (i % P32)] = 0u;
    for (int i = tid; i < 64 * 16; i += 256) {
        int rr = i / 16 + 1, cc = i % 16;
        in32[rr * P32 + (cc < 2 ? cc : 128 + cc)] = 0u;
    }
    const float* src = x + (size_t)b * 3 * 4096;
    for (int p = tid; p < 4096; p += 256) {
        int y = p >> 6, xx = p & 63;
        int dst = (y + 1) * P32 + (xx + 1) * 2;
        in32[dst]     = pkbf(src[p], src[4096 + p]);
        in32[dst + 1] = pkbf(src[8192 + p], 0.f);
    }
    if (tid < OCP) b_s[tid] = (tid < OCR) ? bias[tid] : 0.f;
    __syncthreads();

    int lane = tid & 31, warp = tid >> 5;
    int g = lane >> 2, t = lane & 3;
    int dy = g >> 2, dxl = g & 3;
    uint32_t* outp = outb + (size_t)b * 32 * 32 * (OCR / 2);

    for (int s = warp; s < 128; s += 8) {
        int ty = s >> 3, tx0 = (2 * s) & 15;
        const uint32_t* ab = in32 + (ty * 4 + dy) * P32 + (tx0 * 4 + dxl) * 2 + t;
        float acc[2][NF][4];
        #pragma unroll
        for (int j = 0; j < 2; j++)
            #pragma unroll
            for (int nf = 0; nf < NF; nf++)
                #pragma unroll
                for (int q = 0; q < 4; q++) acc[j][nf][q] = 0.f;

        #pragma unroll
        for (int ky = 0; ky < 3; ky++) {
            const uint32_t* ap = ab + ky * P32;
            uint32_t a00 = ap[0], a01 = ap[2 * P32],     a02 = ap[4],  a03 = ap[2 * P32 + 4];
            uint32_t a10 = ap[8], a11 = ap[2 * P32 + 8], a12 = ap[12], a13 = ap[2 * P32 + 12];
            const uint32_t* bp = B32 + ky * 8 * SB + t * SB + g;
            #pragma unroll
            for (int nf = 0; nf < NF; nf++) {
                uint32_t b0 = bp[nf * 8], b1 = bp[4 * SB + nf * 8];
                mma16(acc[0][nf], a00, a01, a02, a03, b0, b1);
                mma16(acc[1][nf], a10, a11, a12, a13, b0, b1);
            }
        }
        epi_pk<OCR, 32, LEAKY>(acc[0], NF, ty, tx0,     g, t, b_s, outp);
        epi_pk<OCR, 32, LEAKY>(acc[1], NF, ty, tx0 + 1, g, t, b_s, outp);
    }
}

__global__ __launch_bounds__(256) void conv_first_fused(
        const float* __restrict__ x_s, const uint32_t* __restrict__ bf1,
        const float* __restrict__ Wsb,
        const float* __restrict__ x_p, const uint32_t* __restrict__ bfp,
        const float* __restrict__ Pcb, const int* __restrict__ dom,
        uint32_t* __restrict__ s1, uint32_t* __restrict__ p1) {
    if (blockIdx.x < 1024)
        conv_first_body<36, 40, false, false>(blockIdx.x, x_s, bf1, Wsb, nullptr, s1);
    else
        conv_first_body<12, 16, true, true>(blockIdx.x - 1024, x_p, bfp, Pcb, dom, p1);
}

// ---------------------------------------------------------------------------
// Mid conv 32->16: 2 half-image CTAs per image (18-row window). NHWC bf16 out.
// ---------------------------------------------------------------------------
__global__ __launch_bounds__(256) void conv_mid32_k(const __nv_bfloat16* __restrict__ in,
                                                    const float* __restrict__ bias,
                                                    const uint32_t* __restrict__ bmid,
                                                    uint32_t* __restrict__ outb) {
    constexpr int P32 = 688, RL = 18;
    extern __shared__ uint32_t sm32[];
    uint32_t* in32 = sm32;                     // 18*688
    uint32_t* B32  = sm32 + RL * P32;          // 7680
    float*    b_s  = (float*)(B32 + 7680);

    int b = blockIdx.x >> 1, h = blockIdx.x & 1, tid = threadIdx.x;
    {
        uint4* B4 = (uint4*)B32;
        const uint4* pb4 = (const uint4*)bmid;
        for (int i = tid; i < 1920; i += 256) B4[i] = pb4[i];
    }
    int lr_bad = h ? 17 : 0;
    for (int i = tid; i < P32; i += 256) in32[lr_bad * P32 + i] = 0u;
    for (int i = tid; i < RL * 48; i += 256) {
        int lr = i / 48, cc = i % 48;
        in32[lr * P32 + (cc < 20 ? cc : 660 + (cc - 20))] = 0u;
    }
    const uint2* src2 = (const uint2*)(in + (size_t)b * 32 * 32 * 36);
    uint2* dst2 = (uint2*)in32;
    for (int i = tid; i < 17 * 32 * 10; i += 256) {
        int lrv = i / 320, rem = i - lrv * 320;
        int xx = rem / 10, q = rem - xx * 10;
        int lr = lrv + (h ? 0 : 1);
        int gy = h * 16 - 1 + lr;
        uint2 v = (q < 9) ? src2[(gy * 32 + xx) * 9 + q] : make_uint2(0u, 0u);
        dst2[((lr * P32 + (xx + 1) * 20) >> 1) + q] = v;
    }
    if (tid < 40) b_s[tid] = (tid < 36) ? bias[tid] : 0.f;
    __syncthreads();

    int lane = tid & 31, warp = tid >> 5;
    int g = lane >> 2, t = lane & 3;
    int r = lane & 15, kh = lane >> 4;
    int rowz = ((r & 7) >> 2) + 2 * (r >> 3);
    int colp = r & 3;
    uint32_t sbase = (uint32_t)__cvta_generic_to_shared(in32);
    uint32_t* outp = outb + (size_t)b * 16 * 16 * 18;

    for (int s = warp; s < 16; s += 8) {
        int ty_l = (2 * s) / 8, tx0 = (2 * s) % 8;
        uint32_t abase = sbase + ((ty_l * 4 + rowz) * P32 + (tx0 * 4 + colp) * 20 + kh * 4) * 4;
        float acc[2][5][4];
        #pragma unroll
        for (int j = 0; j < 2; j++)
            #pragma unroll
            for (int nf = 0; nf < 5; nf++)
                #pragma unroll
                for (int q = 0; q < 4; q++) acc[j][nf][q] = 0.f;

        #pragma unroll
        for (int ky = 0; ky < 3; ky++) {
            uint32_t kbase = abase + ky * (P32 * 4);
            #pragma unroll
            for (int f = 0; f < 8; f++) {
                uint32_t A0[4], A1[4];
                ldsm4(A0, kbase + f * 32);
                ldsm4(A1, kbase + f * 32 + 320);
                const uint32_t* bp = B32 + ky * 2560 + (f * 8 + t) * 40 + g;
                #pragma unroll
                for (int nf = 0; nf < 5; nf++) {
                    uint32_t b0 = bp[nf * 8], b1 = bp[160 + nf * 8];
                    mma16(acc[0][nf], A0[0], A0[1], A0[2], A0[3], b0, b1);
                    mma16(acc[1][nf], A1[0], A1[1], A1[2], A1[3], b0, b1);
                }
            }
        }
        epi_pk<36, 16, false>(acc[0], 5, ty_l + h * 4, tx0,     g, t, b_s, outp);
        epi_pk<36, 16, false>(acc[1], 5, ty_l + h * 4, tx0 + 1, g, t, b_s, outp);
    }
}

// ---------------------------------------------------------------------------
// Mid conv 16->8: 4 images per block (weights staged once). NHWC bf16 out.
// ---------------------------------------------------------------------------
__global__ __launch_bounds__(256) void conv_mid16_k(const __nv_bfloat16* __restrict__ in,
                                                    const float* __restrict__ bias,
                                                    const uint32_t* __restrict__ bmid,
                                                    uint32_t* __restrict__ outb) {
    constexpr int P32 = 368, ROWS = 18, HH = 16;
    extern __shared__ uint32_t sm32[];
    uint32_t* in32 = sm32;                     // 18*368
    uint32_t* B32  = sm32 + ROWS * P32;        // 7680
    float*    b_s  = (float*)(B32 + 7680);

    int tid = threadIdx.x;
    {
        uint4* B4 = (uint4*)B32;
        const uint4* pb4 = (const uint4*)bmid;
        for (int i = tid; i < 1920; i += 256) B4[i] = pb4[i];
    }
    for (int i = tid; i < 2 * P32; i += 256)
        in32[(i < P32 ? 0 : ROWS - 1) * P32 + (i % P32)] = 0u;
    for (int i = tid; i < HH * 48; i += 256) {
        int rr = i / 48 + 1, cc = i % 48;
        in32[rr * P32 + (cc < 20 ? cc : (HH + 1) * 20 + (cc - 20))] = 0u;
    }
    if (tid < 40) b_s[tid] = (tid < 36) ? bias[tid] : 0.f;

    int lane = tid & 31, warp = tid >> 5;
    int g = lane >> 2, t = lane & 3;
    int r = lane & 15, kh = lane >> 4;
    int rowz = ((r & 7) >> 2) + 2 * (r >> 3);
    int colp = r & 3;
    uint32_t sbase = (uint32_t)__cvta_generic_to_shared(in32);

    for (int im = 0; im < 4; im++) {
        int b = blockIdx.x * 4 + im;
        __syncthreads();                       // smem safe to overwrite / ready
        const uint2* src2 = (const uint2*)(in + (size_t)b * HH * HH * 36);
        uint2* dst2 = (uint2*)in32;
        for (int i = tid; i < HH * HH * 10; i += 256) {
            int p = i / 10, q = i - p * 10;
            int y = p / HH, xx = p % HH;
            uint2 v = (q < 9) ? src2[p * 9 + q] : make_uint2(0u, 0u);
            dst2[(((y + 1) * P32 + (xx + 1) * 20) >> 1) + q] = v;
        }
        __syncthreads();

        uint32_t* outp = outb + (size_t)b * 8 * 8 * 18;
        int s = warp;                          // 8 steps, 1 per warp
        int ty = (2 * s) / 4, tx0 = (2 * s) % 4;
        uint32_t abase = sbase + ((ty * 4 + rowz) * P32 + (tx0 * 4 + colp) * 20 + kh * 4) * 4;
        float acc[2][5][4];
        #pragma unroll
        for (int j = 0; j < 2; j++)
            #pragma unroll
            for (int nf = 0; nf < 5; nf++)
                #pragma unroll
                for (int q = 0; q < 4; q++) acc[j][nf][q] = 0.f;

        #pragma unroll
        for (int ky = 0; ky < 3; ky++) {
            uint32_t kbase = abase + ky * (P32 * 4);
            #pragma unroll
            for (int f = 0; f < 8; f++) {
                uint32_t A0[4], A1[4];
                ldsm4(A0, kbase + f * 32);
                ldsm4(A1, kbase + f * 32 + 320);
                const uint32_t* bp = B32 + ky * 2560 + (f * 8 + t) * 40 + g;
                #pragma unroll
                for (int nf = 0; nf < 5; nf++) {
                    uint32_t b0 = bp[nf * 8], b1 = bp[160 + nf * 8];
                    mma16(acc[0][nf], A0[0], A0[1], A0[2], A0[3], b0, b1);
                    mma16(acc[1][nf], A1[0], A1[1], A1[2], A1[3], b0, b1);
                }
            }
        }
        epi_pk<36, 8, false>(acc[0], 5, ty, tx0,     g, t, b_s, outp);
        epi_pk<36, 8, false>(acc[1], 5, ty, tx0 + 1, g, t, b_s, outp);
    }
}

// ---------------------------------------------------------------------------
// Fused FCs, SMEM-free (weights L2-resident, read via LDG with deep MLP).
// blocks [0,128): shared fc (bf16 NHWC in, f32 g_fw, K=2304, relu) -> g_h
// blocks [128,256): private fc (bf16 NHWC in, f32 g_pw, K=12288) -> g_pf
// ---------------------------------------------------------------------------
__device__ void fc_shared_body(int b, const __nv_bfloat16* __restrict__ in,
                               const float* __restrict__ fw,
                               const float* __restrict__ bias,
                               float* __restrict__ out) {
    int tid = threadIdx.x, lane = tid & 31, warp = tid >> 5;
    int smp = b * 8 + warp;
    const uint2* x2 = (const uint2*)(in + (size_t)smp * 2304);
    float acc[12];
    #pragma unroll
    for (int o = 0; o < 12; o++) acc[o] = 0.f;
    #pragma unroll 2
    for (int i = 0; i < 18; i++) {
        int k4 = lane + i * 32;
        uint2 xa = x2[k4];
        float2 x01 = __bfloat1622float2(*(const __nv_bfloat162*)&xa.x);
        float2 x23 = __bfloat1622float2(*(const __nv_bfloat162*)&xa.y);
        #pragma unroll
        for (int o = 0; o < 12; o++) {
            float4 wa = ((const float4*)(fw + o * 2304))[k4];
            acc[o] = fmaf(x01.x, wa.x, fmaf(x01.y, wa.y,
                      fmaf(x23.x, wa.z, fmaf(x23.y, wa.w, acc[o]))));
        }
    }
    #pragma unroll
    for (int o = 0; o < 12; o++)
        #pragma unroll
        for (int off = 16; off; off >>= 1)
            acc[o] += __shfl_down_sync(0xffffffffu, acc[o], off);
    if (lane == 0)
        #pragma unroll
        for (int o = 0; o < 12; o++)
            out[smp * 12 + o] = fmaxf(acc[o] + bias[o], 0.f);
}

__device__ void fc_priv_body(int b, const __nv_bfloat16* __restrict__ in,
                             const float* __restrict__ pw,
                             const float* __restrict__ bias,
                             const int* __restrict__ dom,
                             float* __restrict__ out) {
    int d = *dom;
    int tid = threadIdx.x, lane = tid & 31, warp = tid >> 5;
    int smp = b * 8 + warp;
    const uint2* x2 = (const uint2*)(in + (size_t)smp * 12288);
    float acc[12];
    #pragma unroll
    for (int o = 0; o < 12; o++) acc[o] = 0.f;
    #pragma unroll 2
    for (int i = 0; i < 96; i++) {
        int k4 = lane + i * 32;
        uint2 xa = x2[k4];
        float2 x01 = __bfloat1622float2(*(const __nv_bfloat162*)&xa.x);
        float2 x23 = __bfloat1622float2(*(const __nv_bfloat162*)&xa.y);
        #pragma unroll
        for (int o = 0; o < 12; o++) {
            float4 wa = ((const float4*)(pw + o * 12288))[k4];
            acc[o] = fmaf(x01.x, wa.x, fmaf(x01.y, wa.y,
                      fmaf(x23.x, wa.z, fmaf(x23.y, wa.w, acc[o]))));
        }
    }
    #pragma unroll
    for (int o = 0; o < 12; o++)
        #pragma unroll
        for (int off = 16; off; off >>= 1)
            acc[o] += __shfl_down_sync(0xffffffffu, acc[o], off);
    if (lane == 0)
        #pragma unroll
        for (int o = 0; o < 12; o++)
            out[smp * 12 + o] = acc[o] + bias[d * 12 + o];
}

__global__ __launch_bounds__(256) void fc_fused(
        const __nv_bfloat16* __restrict__ s3, const float* __restrict__ fw,
        const float* __restrict__ bfc, float* __restrict__ hb,
        const __nv_bfloat16* __restrict__ p1, const float* __restrict__ pw,
        const float* __restrict__ Plb, const int* __restrict__ dom,
        float* __restrict__ pf) {
    if (blockIdx.x < 128) fc_shared_body(blockIdx.x, s3, fw, bfc, hb);
    else                  fc_priv_body(blockIdx.x - 128, p1, pw, Plb, dom, pf);
}

// ---------------------------------------------------------------------------
// Per-sample task-routed heads.
// ---------------------------------------------------------------------------
__global__ void heads_k(const float* __restrict__ h, const float* __restrict__ p,
                        const int* __restrict__ tt,
                        const float* __restrict__ W1, const float* __restrict__ b1,
                        const float* __restrict__ W2, const float* __restrict__ b2,
                        const float* __restrict__ W3, const float* __restrict__ b3,
                        float* __restrict__ out) {
    int bi = blockIdx.x * blockDim.x + threadIdx.x;
    if (bi >= 1024) return;
    int t = tt[bi];
    float x[24];
    #pragma unroll
    for (int i = 0; i < 12; i++) { x[i] = h[bi * 12 + i]; x[12 + i] = p[bi * 12 + i]; }
    float h1[28];
    const float* w1 = W1 + t * 28 * 24;
    #pragma unroll
    for (int i = 0; i < 28; i++) {
        float s = b1[t * 28 + i];
        #pragma unroll
        for (int j = 0; j < 24; j++) s = fmaf(w1[i * 24 + j], x[j], s);
        h1[i] = fmaxf(s, 0.f);
    }
    float h2[14];
    const float* w2 = W2 + t * 14 * 28;
    #pragma unroll
    for (int i = 0; i < 14; i++) {
        float s = b2[t * 14 + i];
        #pragma unroll
        for (int j = 0; j < 28; j++) s = fmaf(w2[i * 28 + j], h1[j], s);
        h2[i] = fmaxf(s, 0.f);
    }
    const float* w3 = W3 + t * 5 * 14;
    #pragma unroll
    for (int i = 0; i < 5; i++) {
        float s = b3[t * 5 + i];
        #pragma unroll
        for (int j = 0; j < 14; j++) s = fmaf(w3[i * 14 + j], h2[j], s);
        out[bi * 5 + i] = s;
    }
}

// ---------------------------------------------------------------------------
// Launch
// ---------------------------------------------------------------------------
extern "C" void kernel_launch(void* const* d_in, const int* in_sizes, int n_in,
                              void* d_out, int out_size) {
    const float* x_s      = (const float*)d_in[0];
    const float* x_p      = (const float*)d_in[1];
    const int*   tt       = (const int*)  d_in[2];
    const int*   dom      = (const int*)  d_in[3];
    const float* Ws_in_W  = (const float*)d_in[4];
    const float* Ws_in_b  = (const float*)d_in[5];
    const float* Ws_hid_W = (const float*)d_in[6];
    const float* Ws_hid_b = (const float*)d_in[7];
    const float* Ws_fc_W  = (const float*)d_in[8];
    const float* Ws_fc_b  = (const float*)d_in[9];
    const float* Pc_W     = (const float*)d_in[10];
    const float* Pc_b     = (const float*)d_in[11];
    const float* Pl_W     = (const float*)d_in[12];
    const float* Pl_b     = (const float*)d_in[13];
    const float* H1W      = (const float*)d_in[14];
    const float* H1b      = (const float*)d_in[15];
    const float* H2W      = (const float*)d_in[16];
    const float* H2b      = (const float*)d_in[17];
    const float* H3W      = (const float*)d_in[18];
    const float* H3b      = (const float*)d_in[19];
    float* out = (float*)d_out;

    __nv_bfloat16 *s1, *s2, *s3, *p1;
    float *hb, *pf, *pw, *fw;
    uint32_t *bf1, *bfp, *bmid;
    cudaGetSymbolAddress((void**)&s1, g_s1);
    cudaGetSymbolAddress((void**)&s2, g_s2);
    cudaGetSymbolAddress((void**)&s3, g_s3);
    cudaGetSymbolAddress((void**)&hb, g_h);
    cudaGetSymbolAddress((void**)&p1, g_p1);
    cudaGetSymbolAddress((void**)&pf, g_pf);
    cudaGetSymbolAddress((void**)&pw, g_pw);
    cudaGetSymbolAddress((void**)&fw, g_fw);
    cudaGetSymbolAddress((void**)&bf1, g_bf1);
    cudaGetSymbolAddress((void**)&bfp, g_bfp);
    cudaGetSymbolAddress((void**)&bmid, g_bmid);

    const int SM_CF  = (66 * 144 + 960 + 40) * 4;            // 42016
    const int SM_S32 = (18 * 688 + 7680 + 40) * 4;           // 80416
    const int SM_M16 = (18 * 368 + 7680 + 40) * 4;           // 57376

    cudaFuncSetAttribute((const void*)conv_first_fused,
                         cudaFuncAttributeMaxDynamicSharedMemorySize, SM_CF);
    cudaFuncSetAttribute((const void*)conv_mid32_k,
                         cudaFuncAttributeMaxDynamicSharedMemorySize, SM_S32);
    cudaFuncSetAttribute((const void*)conv_mid16_k,
                         cudaFuncAttributeMaxDynamicSharedMemorySize, SM_M16);

    prep_k<<<64, 256>>>(Ws_in_W, Pc_W, dom, Ws_hid_W, Pl_W, Ws_fc_W,
                        pw, fw, bf1, bfp, bmid);
    conv_first_fused<<<2048, 256, SM_CF>>>(x_s, bf1, Ws_in_b,
                                           x_p, bfp, Pc_b, dom,
                                           (uint32_t*)s1, (uint32_t*)p1);
    conv_mid32_k<<<2048, 256, SM_S32>>>(s1, Ws_hid_b, bmid, (uint32_t*)s2);
    conv_mid16_k<<<256, 256, SM_M16>>>(s2, Ws_hid_b, bmid, (uint32_t*)s3);
    fc_fused<<<256, 256>>>(s3, fw, Ws_fc_b, hb, p1, pw, Pl_b, dom, pf);
    heads_k<<<4, 256>>>(hb, pf, tt, H1W, H1b, H2W, H2b, H3W, H3b, out);
}